// round 13
// baseline (speedup 1.0000x reference)
#include <cuda_runtime.h>
#include <cuda_bf16.h>
#include <cuda_fp16.h>
#include <math.h>
#include <stdint.h>

#define TT 2048
#define DD 1024
#define HH 1024
#define NBLK 16
#define LYR 4
#define RANKK 64
#define NMEM 64
#define VV 50304
#define RMS_EPS 1.1920929e-7f
#define SEGLEN 32
#define NSEG 64
#define BSCALE 1024.0f
#define BSCALE_INV 0.0009765625f

// ---------------- scratch (static device arrays; no allocation) ----------------
__device__ float g_x[TT * DD];
__device__ float g_h[TT * DD];
__device__ float g_ud[TT * DD];
__device__ float g_r[TT * DD];
__device__ float g_tmp[TT * RANKK];
__device__ __half g_xh[TT * DD];
__device__ float g_seg[NSEG * DD];
__device__ float g_esc[TT];
__device__ float g_hsc[TT];
__device__ __half g_Bh[(size_t)VV * DD];

// ---------------- helpers ----------------
__device__ __forceinline__ float silu_f(float x) { return x / (1.0f + expf(-x)); }

__device__ __forceinline__ uint32_t smem_u32(const void* p) {
    uint32_t a;
    asm("{ .reg .u64 t; cvta.to.shared.u64 t, %1; cvt.u32.u64 %0, t; }" : "=r"(a) : "l"(p));
    return a;
}

__device__ __forceinline__ void cp16(uint32_t dst, const void* src, int sz) {
    asm volatile("cp.async.cg.shared.global [%0], [%1], 16, %2;"
                 :: "r"(dst), "l"(src), "r"(sz) : "memory");
}
#define CP_COMMIT() asm volatile("cp.async.commit_group;" ::: "memory")

__device__ __forceinline__ void ldsm_x4(unsigned& r0, unsigned& r1, unsigned& r2, unsigned& r3,
                                        uint32_t addr) {
    asm volatile("ldmatrix.sync.aligned.m8n8.x4.shared.b16 {%0,%1,%2,%3}, [%4];"
                 : "=r"(r0), "=r"(r1), "=r"(r2), "=r"(r3) : "r"(addr));
}

__device__ __forceinline__ void up2(float& x, float& y, uint64_t p) {
    asm("mov.b64 {%0,%1}, %2;" : "=f"(x), "=f"(y) : "l"(p));
}
__device__ __forceinline__ uint64_t fma2(uint64_t a, uint64_t b, uint64_t c) {
    uint64_t d;
    asm("fma.rn.f32x2 %0, %1, %2, %3;" : "=l"(d) : "l"(a), "l"(b), "l"(c));
    return d;
}
__device__ __forceinline__ uint64_t pk2(float x, float y) {
    uint64_t r;
    asm("mov.b64 %0, {%1,%2};" : "=l"(r) : "f"(x), "f"(y));
    return r;
}
__device__ __forceinline__ void lds_b64x2(uint64_t& lo, uint64_t& hi, uint32_t addr) {
    asm volatile("ld.shared.v2.b64 {%0,%1}, [%2];" : "=l"(lo), "=l"(hi) : "r"(addr));
}

// XOR swizzle helpers
__device__ __forceinline__ int swz(int k, int o) {       // 64-wide [k][o]
    return k * 64 + (o ^ (((k >> 2) & 7) << 2));
}
__device__ __forceinline__ int swzd(int k, int t) {      // 128-wide dup [k][2t]
    return k * 128 + ((2 * t) ^ (((k >> 2) & 7) << 2));
}

// ---------------- embedding ----------------
__global__ void embed_kernel(const int* __restrict__ idx, const float* __restrict__ wte,
                             const float* __restrict__ wpe, float* __restrict__ x) {
    int t = blockIdx.x;
    int row = idx[t];
    const float4* wrow = (const float4*)(wte + (long)row * DD);
    const float4* prow = (const float4*)(wpe + (long)t * DD);
    float4* xo = (float4*)(x + t * DD);
    for (int d = threadIdx.x; d < DD / 4; d += blockDim.x) {
        float4 a = wrow[d], b = prow[d];
        xo[d] = make_float4(a.x + b.x, a.y + b.y, a.z + b.z, a.w + b.w);
    }
}

// ---------------- rms scale only ----------------
__global__ void rms_scale_kernel(const float* __restrict__ in, float* __restrict__ sc) {
    int t = blockIdx.x;
    int tid = threadIdx.x;
    float4 v = ((const float4*)(in + t * DD))[tid];
    float ss = v.x * v.x + v.y * v.y + v.z * v.z + v.w * v.w;
    __shared__ float red[256];
    red[tid] = ss;
    __syncthreads();
    for (int s = 128; s > 0; s >>= 1) {
        if (tid < s) red[tid] += red[tid + s];
        __syncthreads();
    }
    if (tid == 0) sc[t] = rsqrtf(red[0] / (float)DD + RMS_EPS);
}

// final rmsnorm -> fp16
__global__ void rmsnorm_f16_kernel(const float* __restrict__ in, __half* __restrict__ out) {
    int t = blockIdx.x;
    int tid = threadIdx.x;
    float4 v = ((const float4*)(in + t * DD))[tid];
    float ss = v.x * v.x + v.y * v.y + v.z * v.z + v.w * v.w;
    __shared__ float red[256];
    red[tid] = ss;
    __syncthreads();
    for (int s = 128; s > 0; s >>= 1) {
        if (tid < s) red[tid] += red[tid + s];
        __syncthreads();
    }
    float sc = rsqrtf(red[0] / (float)DD + RMS_EPS);
    __half2 h0 = __floats2half2_rn(v.x * sc, v.y * sc);
    __half2 h1 = __floats2half2_rn(v.z * sc, v.w * sc);
    ((__half2*)(out + t * DD))[tid * 2] = h0;
    ((__half2*)(out + t * DD))[tid * 2 + 1] = h1;
}

// lm_head weights: *1024, fp16
__global__ void f16_convert_kernel(const float* __restrict__ in, __half* __restrict__ out) {
    size_t i = (size_t)blockIdx.x * blockDim.x + threadIdx.x;
    const float4* in4 = (const float4*)in + i * 2;
    float4 a = in4[0], b = in4[1];
    __half h[8];
    h[0] = __float2half_rn(a.x * BSCALE); h[1] = __float2half_rn(a.y * BSCALE);
    h[2] = __float2half_rn(a.z * BSCALE); h[3] = __float2half_rn(a.w * BSCALE);
    h[4] = __float2half_rn(b.x * BSCALE); h[5] = __float2half_rn(b.y * BSCALE);
    h[6] = __float2half_rn(b.z * BSCALE); h[7] = __float2half_rn(b.w * BSCALE);
    ((uint4*)(out + i * 8))[0] = *(uint4*)&h[0];
}

// ============ dual block-diagonal GEMM, K=64, silu (dup-A f32x2) ============
// dynamic smem: As2 [64][128] (32KB), Ws1/Ws2 [64][64] swz (16KB each) = 64KB
#define BD64_SMEM 65536
__global__ void __launch_bounds__(256)
bd64_dual_kernel(const float* __restrict__ in, const float* __restrict__ esc,
                 const float* __restrict__ W1, const float* __restrict__ W2,
                 float* __restrict__ out1, float* __restrict__ out2) {
    extern __shared__ float sm[];
    float* As2 = sm;            // 8192 floats
    float* Ws1 = sm + 8192;     // 4096
    float* Ws2 = sm + 12288;    // 4096
    const int t0 = blockIdx.x * 64;
    const int n = blockIdx.y;
    const int tid = threadIdx.x;
    const int tx = tid & 15, ty = tid >> 4;
    const uint32_t asb = smem_u32(As2), w1b = smem_u32(Ws1), w2b = smem_u32(Ws2);

    for (int i = tid; i < 1024; i += 256) {
        int t = i >> 4, kc = (i & 15) << 2;
        float s = esc[t0 + t];
        float4 v = *(const float4*)&in[(t0 + t) * DD + n * 64 + kc];
        v.x *= s; v.y *= s; v.z *= s; v.w *= s;
        int b0 = swzd(kc + 0, t); As2[b0] = v.x; As2[b0 + 1] = v.x;
        int b1 = swzd(kc + 1, t); As2[b1] = v.y; As2[b1 + 1] = v.y;
        int b2 = swzd(kc + 2, t); As2[b2] = v.z; As2[b2 + 1] = v.z;
        int b3 = swzd(kc + 3, t); As2[b3] = v.w; As2[b3 + 1] = v.w;
        float4 w = *(const float4*)&W1[(n * 64 + t) * 64 + kc];
        Ws1[swz(kc + 0, t)] = w.x; Ws1[swz(kc + 1, t)] = w.y;
        Ws1[swz(kc + 2, t)] = w.z; Ws1[swz(kc + 3, t)] = w.w;
        float4 u = *(const float4*)&W2[(n * 64 + t) * 64 + kc];
        Ws2[swz(kc + 0, t)] = u.x; Ws2[swz(kc + 1, t)] = u.y;
        Ws2[swz(kc + 2, t)] = u.z; Ws2[swz(kc + 3, t)] = u.w;
    }
    __syncthreads();

    uint64_t acc1[4][2] = {}, acc2[4][2] = {};
    const int tx4 = tx * 4, ty8 = ty * 8;
#pragma unroll 4
    for (int k = 0; k < 64; k++) {
        const int co = ((k >> 2) & 7) << 2;
        uint64_t a0, a1, a2, a3;
        lds_b64x2(a0, a1, asb + (uint32_t)(k * 128 + (ty8 ^ co)) * 4);
        lds_b64x2(a2, a3, asb + (uint32_t)(k * 128 + ((ty8 + 4) ^ co)) * 4);
        uint64_t b1l, b1h, b2l, b2h;
        lds_b64x2(b1l, b1h, w1b + (uint32_t)(k * 64 + (tx4 ^ co)) * 4);
        lds_b64x2(b2l, b2h, w2b + (uint32_t)(k * 64 + (tx4 ^ co)) * 4);
        acc1[0][0] = fma2(a0, b1l, acc1[0][0]); acc1[0][1] = fma2(a0, b1h, acc1[0][1]);
        acc1[1][0] = fma2(a1, b1l, acc1[1][0]); acc1[1][1] = fma2(a1, b1h, acc1[1][1]);
        acc1[2][0] = fma2(a2, b1l, acc1[2][0]); acc1[2][1] = fma2(a2, b1h, acc1[2][1]);
        acc1[3][0] = fma2(a3, b1l, acc1[3][0]); acc1[3][1] = fma2(a3, b1h, acc1[3][1]);
        acc2[0][0] = fma2(a0, b2l, acc2[0][0]); acc2[0][1] = fma2(a0, b2h, acc2[0][1]);
        acc2[1][0] = fma2(a1, b2l, acc2[1][0]); acc2[1][1] = fma2(a1, b2h, acc2[1][1]);
        acc2[2][0] = fma2(a2, b2l, acc2[2][0]); acc2[2][1] = fma2(a2, b2h, acc2[2][1]);
        acc2[3][0] = fma2(a3, b2l, acc2[3][0]); acc2[3][1] = fma2(a3, b2h, acc2[3][1]);
    }
#pragma unroll
    for (int q = 0; q < 4; q++) {
        int row = t0 + ty * 4 + q;
        float x0, x1, x2, x3;
        up2(x0, x1, acc1[q][0]); up2(x2, x3, acc1[q][1]);
        *(float4*)&out1[row * HH + n * 64 + tx4] =
            make_float4(silu_f(x0), silu_f(x1), silu_f(x2), silu_f(x3));
        up2(x0, x1, acc2[q][0]); up2(x2, x3, acc2[q][1]);
        *(float4*)&out2[row * HH + n * 64 + tx4] =
            make_float4(silu_f(x0), silu_f(x1), silu_f(x2), silu_f(x3));
    }
}

// ============ block-diagonal GEMM, K=192 (wpost), silu, virtual concat ============
// Reads hn/e/shifted directly: chunk (n,c) -> part = (3n+c)>>4, col = ((3n+c)&15)*64
__global__ void __launch_bounds__(256)
bd192_kernel(const float* __restrict__ h, const float* __restrict__ hsc,
             const float* __restrict__ x, const float* __restrict__ esc,
             const float* __restrict__ W, float* __restrict__ out) {
    __shared__ float As2[64 * 128];
    __shared__ float Ws[64 * 64];
    const int t0 = blockIdx.x * 64;
    const int n = blockIdx.y;
    const int tid = threadIdx.x;
    const int tx = tid & 15, ty = tid >> 4;
    const uint32_t asb = smem_u32(As2), wsb = smem_u32(Ws);
    const int tx4 = tx * 4, ty8 = ty * 8;

    uint64_t acc[4][2] = {};
    for (int c = 0; c < 3; c++) {
        const int pc = 3 * n + c;
        const int part = pc >> 4;
        const int colo = (pc & 15) << 6;
        for (int i = tid; i < 1024; i += 256) {
            int tl = i >> 4, kc = (i & 15) << 2;
            int trow = t0 + tl;
            float4 v;
            float s;
            if (part == 0) {
                v = *(const float4*)&h[trow * DD + colo + kc];
                s = hsc[trow];
            } else if (part == 1) {
                v = *(const float4*)&x[trow * DD + colo + kc];
                s = esc[trow];
            } else {
                if (trow == 0) {
                    v = make_float4(0.f, 0.f, 0.f, 0.f);
                    s = 0.f;
                } else {
                    v = *(const float4*)&x[(trow - 1) * DD + colo + kc];
                    s = esc[trow - 1];
                }
            }
            v.x *= s; v.y *= s; v.z *= s; v.w *= s;
            int b0 = swzd(kc + 0, tl); As2[b0] = v.x; As2[b0 + 1] = v.x;
            int b1 = swzd(kc + 1, tl); As2[b1] = v.y; As2[b1 + 1] = v.y;
            int b2 = swzd(kc + 2, tl); As2[b2] = v.z; As2[b2 + 1] = v.z;
            int b3 = swzd(kc + 3, tl); As2[b3] = v.w; As2[b3 + 1] = v.w;
            float4 w = *(const float4*)&W[(n * 64 + tl) * 192 + c * 64 + kc];
            Ws[swz(kc + 0, tl)] = w.x; Ws[swz(kc + 1, tl)] = w.y;
            Ws[swz(kc + 2, tl)] = w.z; Ws[swz(kc + 3, tl)] = w.w;
        }
        __syncthreads();
#pragma unroll 4
        for (int k = 0; k < 64; k++) {
            const int co = ((k >> 2) & 7) << 2;
            uint64_t a0, a1, a2, a3;
            lds_b64x2(a0, a1, asb + (uint32_t)(k * 128 + (ty8 ^ co)) * 4);
            lds_b64x2(a2, a3, asb + (uint32_t)(k * 128 + ((ty8 + 4) ^ co)) * 4);
            uint64_t bl, bh;
            lds_b64x2(bl, bh, wsb + (uint32_t)(k * 64 + (tx4 ^ co)) * 4);
            acc[0][0] = fma2(a0, bl, acc[0][0]); acc[0][1] = fma2(a0, bh, acc[0][1]);
            acc[1][0] = fma2(a1, bl, acc[1][0]); acc[1][1] = fma2(a1, bh, acc[1][1]);
            acc[2][0] = fma2(a2, bl, acc[2][0]); acc[2][1] = fma2(a2, bh, acc[2][1]);
            acc[3][0] = fma2(a3, bl, acc[3][0]); acc[3][1] = fma2(a3, bh, acc[3][1]);
        }
        __syncthreads();
    }
#pragma unroll
    for (int q = 0; q < 4; q++) {
        int row = t0 + ty * 4 + q;
        float x0, x1, x2, x3;
        up2(x0, x1, acc[q][0]); up2(x2, x3, acc[q][1]);
        *(float4*)&out[row * HH + n * 64 + tx4] =
            make_float4(silu_f(x0), silu_f(x1), silu_f(x2), silu_f(x3));
    }
}

// ============ residual update (dup-A f32x2) ============
__global__ void __launch_bounds__(256)
update_kernel(float* __restrict__ x, const float* __restrict__ r,
              const float* __restrict__ tmp, const float* __restrict__ wlocal,
              const float* __restrict__ lowA) {
    __shared__ float As2[64 * 128];
    __shared__ float Ws[64 * 64];
    const int t0 = blockIdx.x * 64;
    const int n = blockIdx.y;
    const int tid = threadIdx.x;
    const int tx = tid & 15, ty = tid >> 4;
    const uint32_t asb = smem_u32(As2), wsb = smem_u32(Ws);
    const int tx4 = tx * 4, ty8 = ty * 8;

    uint64_t acc[4][2] = {};
    for (int ph = 0; ph < 2; ph++) {
        for (int i = tid; i < 1024; i += 256) {
            int tl = i >> 4, kc = (i & 15) << 2;
            float4 v = (ph == 0)
                           ? *(const float4*)&r[(t0 + tl) * HH + n * 64 + kc]
                           : *(const float4*)&tmp[(t0 + tl) * RANKK + kc];
            int b0 = swzd(kc + 0, tl); As2[b0] = v.x; As2[b0 + 1] = v.x;
            int b1 = swzd(kc + 1, tl); As2[b1] = v.y; As2[b1 + 1] = v.y;
            int b2 = swzd(kc + 2, tl); As2[b2] = v.z; As2[b2 + 1] = v.z;
            int b3 = swzd(kc + 3, tl); As2[b3] = v.w; As2[b3 + 1] = v.w;
            float4 w = (ph == 0)
                           ? *(const float4*)&wlocal[(n * 64 + tl) * 64 + kc]
                           : *(const float4*)&lowA[(n * 64 + tl) * RANKK + kc];
            Ws[swz(kc + 0, tl)] = w.x; Ws[swz(kc + 1, tl)] = w.y;
            Ws[swz(kc + 2, tl)] = w.z; Ws[swz(kc + 3, tl)] = w.w;
        }
        __syncthreads();
#pragma unroll 4
        for (int k = 0; k < 64; k++) {
            const int co = ((k >> 2) & 7) << 2;
            uint64_t a0, a1, a2, a3;
            lds_b64x2(a0, a1, asb + (uint32_t)(k * 128 + (ty8 ^ co)) * 4);
            lds_b64x2(a2, a3, asb + (uint32_t)(k * 128 + ((ty8 + 4) ^ co)) * 4);
            uint64_t bl, bh;
            lds_b64x2(bl, bh, wsb + (uint32_t)(k * 64 + (tx4 ^ co)) * 4);
            acc[0][0] = fma2(a0, bl, acc[0][0]); acc[0][1] = fma2(a0, bh, acc[0][1]);
            acc[1][0] = fma2(a1, bl, acc[1][0]); acc[1][1] = fma2(a1, bh, acc[1][1]);
            acc[2][0] = fma2(a2, bl, acc[2][0]); acc[2][1] = fma2(a2, bh, acc[2][1]);
            acc[3][0] = fma2(a3, bl, acc[3][0]); acc[3][1] = fma2(a3, bh, acc[3][1]);
        }
        __syncthreads();
    }
#pragma unroll
    for (int q = 0; q < 4; q++) {
        int row = t0 + ty * 4 + q;
        float x0, x1, x2, x3;
        up2(x0, x1, acc[q][0]); up2(x2, x3, acc[q][1]);
        float4* px = (float4*)&x[row * DD + n * 64 + tx4];
        float4 v = *px;
        v.x += x0; v.y += x1; v.z += x2; v.w += x3;
        *px = v;
    }
}

// ============ lowrank stage 1 ============
__global__ void __launch_bounds__(256)
lowrank1_kernel(const float* __restrict__ r, const float* __restrict__ lowB,
                float* __restrict__ tmp) {
    __shared__ float As[16 * 64];
    __shared__ float Ws[64 * 64];
    const int t0 = blockIdx.x * 16;
    const int tid = threadIdx.x;
    const int tx = tid & 15, ty = tid >> 4;
    const uint32_t wsb = smem_u32(Ws);
    const int tx4 = tx * 4;
    uint64_t acc[2] = {};
    for (int c = 0; c < 16; c++) {
        {
            int t = tid >> 4, kc = (tid & 15) << 2;
            *(float4*)&As[t * 64 + kc] = *(const float4*)&r[(t0 + t) * HH + c * 64 + kc];
        }
        for (int i = tid; i < 1024; i += 256) {
            int o = i >> 4, kc = (i & 15) << 2;
            float4 w = *(const float4*)&lowB[o * HH + c * 64 + kc];
            Ws[swz(kc + 0, o)] = w.x; Ws[swz(kc + 1, o)] = w.y;
            Ws[swz(kc + 2, o)] = w.z; Ws[swz(kc + 3, o)] = w.w;
        }
        __syncthreads();
#pragma unroll 8
        for (int k = 0; k < 64; k++) {
            const int co = ((k >> 2) & 7) << 2;
            float a = As[ty * 64 + k];
            uint64_t ap = pk2(a, a);
            uint64_t bl, bh;
            lds_b64x2(bl, bh, wsb + (uint32_t)(k * 64 + (tx4 ^ co)) * 4);
            acc[0] = fma2(ap, bl, acc[0]);
            acc[1] = fma2(ap, bh, acc[1]);
        }
        __syncthreads();
    }
    float x0, x1, x2, x3;
    up2(x0, x1, acc[0]); up2(x2, x3, acc[1]);
    *(float4*)&tmp[(t0 + ty) * RANKK + tx4] = make_float4(x0, x1, x2, x3);
}

// ============ causal scan, 3-phase chunked ============
__global__ void scanA_kernel(float* __restrict__ buf, const float* __restrict__ logA,
                             const float* __restrict__ logdt, float* __restrict__ seg) {
    int d = blockIdx.x * 32 + threadIdx.x;
    int s = blockIdx.y * 8 + threadIdx.y;
    float a = expf(-expf(logA[d]) * expf(logdt[d]));
    float y = 0.f;
    int t0 = s * SEGLEN;
#pragma unroll 8
    for (int tt = 0; tt < SEGLEN; tt++) {
        int i = (t0 + tt) * DD + d;
        y = a * y + buf[i];
        buf[i] = y;
    }
    seg[s * DD + d] = y;
}

__global__ void scanB_kernel(float* __restrict__ seg, const float* __restrict__ logA,
                             const float* __restrict__ logdt) {
    int d = blockIdx.x * 16 + threadIdx.x;
    int j = threadIdx.y;
    float a = expf(-expf(logA[d]) * expf(logdt[d]));
    float a32 = a;
#pragma unroll
    for (int q = 0; q < 5; q++) a32 *= a32;
    __shared__ float s[NSEG][17];
    float cur = seg[j * DD + d];
    s[j][threadIdx.x] = cur;
    float m = a32;
    for (int st = 1; st < NSEG; st <<= 1) {
        __syncthreads();
        float prev = (j >= st) ? s[j - st][threadIdx.x] : 0.f;
        __syncthreads();
        cur += m * prev;
        s[j][threadIdx.x] = cur;
        m = m * m;
    }
    seg[j * DD + d] = cur;
}

__global__ void scanC_kernel(float* __restrict__ buf, const float* __restrict__ logA,
                             const float* __restrict__ logdt, const float* __restrict__ seg) {
    int d = blockIdx.x * 32 + threadIdx.x;
    int s = blockIdx.y * 8 + threadIdx.y;
    if (s == 0) return;
    float a = expf(-expf(logA[d]) * expf(logdt[d]));
    float carry = seg[(s - 1) * DD + d];
    float f = a;
    int t0 = s * SEGLEN;
#pragma unroll 8
    for (int tt = 0; tt < SEGLEN; tt++) {
        int i = (t0 + tt) * DD + d;
        buf[i] += f * carry;
        f *= a;
    }
}

// ---------------- combine: h = hseq + gain*ud (in place) + row scale ----------------
__global__ void combine_kernel(float* __restrict__ h, const float* __restrict__ udep,
                               const float* __restrict__ logAd, const float* __restrict__ logdtd,
                               const int* __restrict__ pK, float* __restrict__ hsc) {
    int t = blockIdx.x;
    int tid = threadIdx.x;
    int K = *pK;
    float hv[4];
    float ss = 0.f;
#pragma unroll
    for (int r = 0; r < 4; r++) {
        int d = tid + r * 256;
        float g;
        if (d < NMEM) {
            g = (float)K;
        } else {
            float aD = expf(-expf(logAd[d - NMEM]) * expf(logdtd[d - NMEM]));
            float om = 1.f - aD;
            float safe = fmaxf(om, 1e-8f);
            float p = 1.f;
            for (int k = 0; k < K; k++) p *= aD;
            g = (fabsf(om) < 1e-6f) ? (float)K : (1.f - p) / safe;
        }
        float hx = h[t * DD + d] + g * udep[t * DD + d];
        hv[r] = hx;
        ss += hx * hx;
    }
    __shared__ float red[256];
    red[tid] = ss;
    __syncthreads();
    for (int s = 128; s > 0; s >>= 1) {
        if (tid < s) red[tid] += red[tid + s];
        __syncthreads();
    }
#pragma unroll
    for (int r = 0; r < 4; r++) h[t * DD + tid + r * 256] = hv[r];
    if (tid == 0) hsc[t] = rsqrtf(red[0] / (float)DD + RMS_EPS);
}

// ================= LM head GEMM (fp16 m16n8k16, ldmatrix + SW128, 4-stage cp.async) =====
#define A_ST 16384
#define B_ST 32768
#define NSTG 4
#define LM_SMEM (NSTG * (A_ST + B_ST))

#define MMA_F16(c, a, b)                                                               \
    asm volatile(                                                                      \
        "mma.sync.aligned.m16n8k16.row.col.f32.f16.f16.f32 "                           \
        "{%0,%1,%2,%3},{%4,%5,%6,%7},{%8,%9},{%0,%1,%2,%3};\n"                         \
        : "+f"(c[0]), "+f"(c[1]), "+f"(c[2]), "+f"(c[3])                               \
        : "r"(a[0]), "r"(a[1]), "r"(a[2]), "r"(a[3]), "r"(b[0]), "r"(b[1]))

__global__ void __launch_bounds__(256, 1)
lmhead_gemm(const __half* __restrict__ A, const __half* __restrict__ B, float* __restrict__ C) {
    extern __shared__ __align__(16) char smc[];
    const uint32_t smb = smem_u32(smc);
    const int tid = threadIdx.x;
    const int lane = tid & 31;
    const int warp = tid >> 5;
    const int M0 = blockIdx.x * 128;
    const int N0 = blockIdx.y * 256;
    const int nVal = (VV - N0 < 256) ? (VV - N0) : 256;
    const int wm = (warp >> 2) * 64;
    const int wn = (warp & 3) * 64;
    const int rr = lane >> 2;
    const int kc = lane & 3;
    const int l7 = lane & 7;

    float acc[4][8][4];
#pragma unroll
    for (int i = 0; i < 4; i++)
#pragma unroll
        for (int j = 0; j < 8; j++)
#pragma unroll
            for (int k = 0; k < 4; k++) acc[i][j][k] = 0.f;

#define LOAD_STAGE(s, kb)                                                              \
    {                                                                                  \
        _Pragma("unroll") for (int i = 0; i < 4; i++) {                                \
            int cch = tid + i * 256;                                                   \
            int m = cch >> 3, q = cch & 7;                                             \
            uint32_t dst = smb + (s) * A_ST + (uint32_t)(m * 128 + ((q ^ (m & 7)) << 4));\
            const __half* src = A + (size_t)(M0 + m) * DD + (kb) * 64 + q * 8;         \
            cp16(dst, src, 16);                                                        \
        }                                                                              \
        _Pragma("unroll") for (int i = 0; i < 8; i++) {                                \
            int cch = tid + i * 256;                                                   \
            int n = cch >> 3, q = cch & 7;                                             \
            uint32_t dst = smb + NSTG * A_ST + (s) * B_ST +                            \
                           (uint32_t)(n * 128 + ((q ^ (n & 7)) << 4));                 \
            int ok = (n < nVal);                                                       \
            const __half* src = B + (size_t)(N0 + (ok ? n : 0)) * DD + (kb) * 64 + q * 8;\
            cp16(dst, src, ok ? 16 : 0);                                               \
        }                                                                              \
        CP_COMMIT();                                                                   \
    }

    LOAD_STAGE(0, 0);
    LOAD_STAGE(1, 1);
    LOAD_STAGE(2, 2);

    const int a_row = (lane & 15);
    const int a_kh = lane >> 4;
    const int b_row = (lane & 7) + ((lane >> 4) & 1) * 8;
    const int b_kh = (lane >> 3) & 1;

    const int NKB = DD / 64;
    for (int kb = 0; kb < NKB; kb++) {
        const int s = kb & 3;
        if (kb < NKB - 2) {
            asm volatile("cp.async.wait_group 2;" ::: "memory");
        } else if (kb == NKB - 2) {
            asm volatile("cp.async.wait_group 1;" ::: "memory");
        } else {
            asm volatile("cp.async.wait_group 0;" ::: "memory");
        }
        __syncthreads();
        if (kb + 3 < NKB) LOAD_STAGE((kb + 3) & 3, kb + 3);

        const uint32_t Ab = smb + s * A_ST;
        const uint32_t Bb = smb + NSTG * A_ST + s * B_ST;

#pragma unroll
        for (int ks = 0; ks < 4; ks++) {
            unsigned af[4][4], bf[8][2];
#pragma unroll
            for (int mi = 0; mi < 4; mi++) {
                int row = wm + mi * 16 + a_row;
                int chunk = (ks * 2 + a_kh) ^ l7;
                ldsm_x4(af[mi][0], af[mi][1], af[mi][2], af[mi][3],
                        Ab + (uint32_t)(row * 128 + (chunk << 4)));
            }
#pragma unroll
            for (int njp = 0; njp < 4; njp++) {
                int row = wn + njp * 16 + b_row;
                int chunk = (ks * 2 + b_kh) ^ l7;
                ldsm_x4(bf[2 * njp][0], bf[2 * njp][1], bf[2 * njp + 1][0], bf[2 * njp + 1][1],
                        Bb + (uint32_t)(row * 128 + (chunk << 4)));
            }
#pragma unroll
            for (int mi = 0; mi < 4; mi++)
#pragma unroll
                for (int nj = 0; nj < 8; nj++) MMA_F16(acc[mi][nj], af[mi], bf[nj]);
        }
    }

#pragma unroll
    for (int mi = 0; mi < 4; mi++) {
#pragma unroll
        for (int nj = 0; nj < 8; nj++) {
            int c0 = N0 + wn + nj * 8 + (kc << 1);
            if (c0 < VV) {
                size_t r0 = (size_t)(M0 + wm + mi * 16 + rr);
                *(float2*)(C + r0 * VV + c0) =
                    make_float2(acc[mi][nj][0] * BSCALE_INV, acc[mi][nj][1] * BSCALE_INV);
                *(float2*)(C + (r0 + 8) * VV + c0) =
                    make_float2(acc[mi][nj][2] * BSCALE_INV, acc[mi][nj][3] * BSCALE_INV);
            }
        }
    }
}

// ---------------- launcher ----------------
extern "C" void kernel_launch(void* const* d_in, const int* in_sizes, int n_in,
                              void* d_out, int out_size) {
    const int* idx = (const int*)d_in[0];
    const int* pK = (const int*)d_in[1];
    const float* wte = (const float*)d_in[2];
    const float* wpe = (const float*)d_in[3];
    const float* bseq_w = (const float*)d_in[4];
    const float* logA_seq = (const float*)d_in[5];
    const float* logdt_seq = (const float*)d_in[6];
    const float* bdepth_w = (const float*)d_in[7];
    const float* logA_depth = (const float*)d_in[8];
    const float* logdt_depth = (const float*)d_in[9];
    const float* wpost_w = (const float*)d_in[10];
    const float* wlocal_w = (const float*)d_in[11];
    const float* lowA = (const float*)d_in[12];
    const float* lowB = (const float*)d_in[13];
    const float* lm_head_w = (const float*)d_in[14];
    float* out = (float*)d_out;

    float *x, *h, *ud, *r, *tmp, *seg, *esc, *hsc;
    __half *xh, *Bh;
    cudaGetSymbolAddress((void**)&x, g_x);
    cudaGetSymbolAddress((void**)&h, g_h);
    cudaGetSymbolAddress((void**)&ud, g_ud);
    cudaGetSymbolAddress((void**)&r, g_r);
    cudaGetSymbolAddress((void**)&tmp, g_tmp);
    cudaGetSymbolAddress((void**)&seg, g_seg);
    cudaGetSymbolAddress((void**)&esc, g_esc);
    cudaGetSymbolAddress((void**)&hsc, g_hsc);
    cudaGetSymbolAddress((void**)&xh, g_xh);
    cudaGetSymbolAddress((void**)&Bh, g_Bh);

    cudaFuncSetAttribute(lmhead_gemm, cudaFuncAttributeMaxDynamicSharedMemorySize, LM_SMEM);
    cudaFuncSetAttribute(bd64_dual_kernel, cudaFuncAttributeMaxDynamicSharedMemorySize, BD64_SMEM);

    f16_convert_kernel<<<(VV * DD / 8) / 256, 256>>>(lm_head_w, Bh);

    embed_kernel<<<TT, 256>>>(idx, wte, wpe, x);

    for (int l = 0; l < LYR; l++) {
        const float* bseq_l = bseq_w + l * NBLK * 64 * 64;
        const float* lAs = logA_seq + l * HH;
        const float* lDs = logdt_seq + l * HH;
        const float* bdep_l = bdepth_w + l * NBLK * 64 * 64;
        const float* lAd = logA_depth + l * (HH - NMEM);
        const float* lDd = logdt_depth + l * (HH - NMEM);
        const float* wpost_l = wpost_w + l * NBLK * 64 * 192;
        const float* wlocal_l = wlocal_w + l * NBLK * 64 * 64;
        const float* lowA_l = lowA + l * DD * RANKK;
        const float* lowB_l = lowB + l * RANKK * HH;

        rms_scale_kernel<<<TT, 256>>>(x, esc);
        bd64_dual_kernel<<<dim3(TT / 64, NBLK), 256, BD64_SMEM>>>(x, esc, bseq_l, bdep_l, h, ud);
        scanA_kernel<<<dim3(32, 8), dim3(32, 8)>>>(h, lAs, lDs, seg);
        scanB_kernel<<<DD / 16, dim3(16, NSEG)>>>(seg, lAs, lDs);
        scanC_kernel<<<dim3(32, 8), dim3(32, 8)>>>(h, lAs, lDs, seg);
        combine_kernel<<<TT, 256>>>(h, ud, lAd, lDd, pK, hsc);
        bd192_kernel<<<dim3(TT / 64, NBLK), 256>>>(h, hsc, x, esc, wpost_l, r);
        lowrank1_kernel<<<TT / 16, 256>>>(r, lowB_l, tmp);
        update_kernel<<<dim3(TT / 64, NBLK), 256>>>(x, r, tmp, wlocal_l, lowA_l);
    }

    rmsnorm_f16_kernel<<<TT, 256>>>(x, xh);
    lmhead_gemm<<<dim3(TT / 128, (VV + 255) / 256), 256, LM_SMEM>>>(xh, Bh, out);
}

// round 14
// speedup vs baseline: 1.5565x; 1.5565x over previous
#include <cuda_runtime.h>
#include <cuda_bf16.h>
#include <cuda_fp16.h>
#include <math.h>
#include <stdint.h>

#define TT 2048
#define DD 1024
#define HH 1024
#define NBLK 16
#define LYR 4
#define RANKK 64
#define NMEM 64
#define VV 50304
#define RMS_EPS 1.1920929e-7f
#define SEGLEN 32
#define NSEG 64
#define BSCALE 1024.0f
#define BSCALE_INV 0.0009765625f

// ---------------- scratch ----------------
__device__ float g_x[TT * DD];
__device__ float g_h[TT * DD];
__device__ float g_ud[TT * DD];
__device__ float g_seg[NSEG * DD];
__device__ __half g_eh[TT * DD];
__device__ __half g_hn[TT * DD];
__device__ __half g_rh[TT * HH];
__device__ __half g_tmph[TT * RANKK];
__device__ __half g_xh[TT * DD];
__device__ __half g_Bh[(size_t)VV * DD];
__device__ __half g_bseqh[LYR * NBLK * 64 * 64];
__device__ __half g_bdeph[LYR * NBLK * 64 * 64];
__device__ __half g_wposth[LYR * NBLK * 64 * 192];
__device__ __half g_wloch[LYR * NBLK * 64 * 64];
__device__ __half g_lowAh[LYR * DD * RANKK];
__device__ __half g_lowBh[LYR * RANKK * HH];

// ---------------- helpers ----------------
__device__ __forceinline__ float silu_f(float x) { return x / (1.0f + expf(-x)); }

__device__ __forceinline__ uint32_t smem_u32(const void* p) {
    uint32_t a;
    asm("{ .reg .u64 t; cvta.to.shared.u64 t, %1; cvt.u32.u64 %0, t; }" : "=r"(a) : "l"(p));
    return a;
}
__device__ __forceinline__ void cp16(uint32_t dst, const void* src, int sz) {
    asm volatile("cp.async.cg.shared.global [%0], [%1], 16, %2;"
                 :: "r"(dst), "l"(src), "r"(sz) : "memory");
}
#define CP_COMMIT() asm volatile("cp.async.commit_group;" ::: "memory")
#define CP_WAIT0() asm volatile("cp.async.wait_group 0;" ::: "memory")

__device__ __forceinline__ void ldsm_x4(unsigned& r0, unsigned& r1, unsigned& r2, unsigned& r3,
                                        uint32_t addr) {
    asm volatile("ldmatrix.sync.aligned.m8n8.x4.shared.b16 {%0,%1,%2,%3}, [%4];"
                 : "=r"(r0), "=r"(r1), "=r"(r2), "=r"(r3) : "r"(addr));
}

#define MMA_F16(c, a, b)                                                               \
    asm volatile(                                                                      \
        "mma.sync.aligned.m16n8k16.row.col.f32.f16.f16.f32 "                           \
        "{%0,%1,%2,%3},{%4,%5,%6,%7},{%8,%9},{%0,%1,%2,%3};\n"                         \
        : "+f"(c[0]), "+f"(c[1]), "+f"(c[2]), "+f"(c[3])                               \
        : "r"(a[0]), "r"(a[1]), "r"(a[2]), "r"(a[3]), "r"(b[0]), "r"(b[1]))

// SW128 row helpers: row of 64 halves = 128B atom; chunk q stored at q^(row&7)
__device__ __forceinline__ uint32_t sw_off(int row, int q) {
    return (uint32_t)(row * 128 + ((q ^ (row & 7)) << 4));
}

// ---------------- embedding ----------------
__global__ void embed_kernel(const int* __restrict__ idx, const float* __restrict__ wte,
                             const float* __restrict__ wpe, float* __restrict__ x) {
    int t = blockIdx.x;
    int row = idx[t];
    const float4* wrow = (const float4*)(wte + (long)row * DD);
    const float4* prow = (const float4*)(wpe + (long)t * DD);
    float4* xo = (float4*)(x + t * DD);
    for (int d = threadIdx.x; d < DD / 4; d += blockDim.x) {
        float4 a = wrow[d], b = prow[d];
        xo[d] = make_float4(a.x + b.x, a.y + b.y, a.z + b.z, a.w + b.w);
    }
}

// ---------------- rmsnorm -> fp16 ----------------
__global__ void rmsnorm_f16_kernel(const float* __restrict__ in, __half* __restrict__ out) {
    int t = blockIdx.x;
    int tid = threadIdx.x;
    float4 v = ((const float4*)(in + t * DD))[tid];
    float ss = v.x * v.x + v.y * v.y + v.z * v.z + v.w * v.w;
    __shared__ float red[256];
    red[tid] = ss;
    __syncthreads();
    for (int s = 128; s > 0; s >>= 1) {
        if (tid < s) red[tid] += red[tid + s];
        __syncthreads();
    }
    float sc = rsqrtf(red[0] / (float)DD + RMS_EPS);
    __half2 h0 = __floats2half2_rn(v.x * sc, v.y * sc);
    __half2 h1 = __floats2half2_rn(v.z * sc, v.w * sc);
    ((__half2*)(out + t * DD))[tid * 2] = h0;
    ((__half2*)(out + t * DD))[tid * 2 + 1] = h1;
}

// lm_head weights: *1024, fp16
__global__ void f16_convert_kernel(const float* __restrict__ in, __half* __restrict__ out) {
    size_t i = (size_t)blockIdx.x * blockDim.x + threadIdx.x;
    const float4* in4 = (const float4*)in + i * 2;
    float4 a = in4[0], b = in4[1];
    __half h[8];
    h[0] = __float2half_rn(a.x * BSCALE); h[1] = __float2half_rn(a.y * BSCALE);
    h[2] = __float2half_rn(a.z * BSCALE); h[3] = __float2half_rn(a.w * BSCALE);
    h[4] = __float2half_rn(b.x * BSCALE); h[5] = __float2half_rn(b.y * BSCALE);
    h[6] = __float2half_rn(b.z * BSCALE); h[7] = __float2half_rn(b.w * BSCALE);
    ((uint4*)(out + i * 8))[0] = *(uint4*)&h[0];
}

// generic fp16 convert (natural scale)
__global__ void conv_f16_kernel(const float* __restrict__ in, __half* __restrict__ out) {
    size_t i = (size_t)blockIdx.x * blockDim.x + threadIdx.x;
    const float4* in4 = (const float4*)in + i * 2;
    float4 a = in4[0], b = in4[1];
    __half h[8];
    h[0] = __float2half_rn(a.x); h[1] = __float2half_rn(a.y);
    h[2] = __float2half_rn(a.z); h[3] = __float2half_rn(a.w);
    h[4] = __float2half_rn(b.x); h[5] = __float2half_rn(b.y);
    h[6] = __float2half_rn(b.z); h[7] = __float2half_rn(b.w);
    ((uint4*)(out + i * 8))[0] = *(uint4*)&h[0];
}

// ======== bd64 dual: h=silu(e@W1^T), ud=silu(e@W2^T). M=128, N=128(W1|W2), K=64 =========
__global__ void __launch_bounds__(256)
bd64_f16_kernel(const __half* __restrict__ eh, const __half* __restrict__ W1h,
                const __half* __restrict__ W2h, float* __restrict__ h, float* __restrict__ ud) {
    __shared__ __half Ash[128 * 64];
    __shared__ __half Bsh[128 * 64];
    const int t0 = blockIdx.x * 128;
    const int n = blockIdx.y;
    const int tid = threadIdx.x;
    const int lane = tid & 31;
    const int warp = tid >> 5;
    const uint32_t Ab = smem_u32(Ash), Bb = smem_u32(Bsh);
    const int wm = (warp >> 1) * 32;
    const int wn = (warp & 1) * 64;
    const int rr = lane >> 2, kc = lane & 3, l7 = lane & 7;

#pragma unroll
    for (int i = 0; i < 4; i++) {
        int cch = tid + i * 256;
        int m = cch >> 3, q = cch & 7;
        cp16(Ab + sw_off(m, q), eh + (size_t)(t0 + m) * DD + n * 64 + q * 8, 16);
        const __half* wsrc = (m < 64) ? (W1h + (n * 64 + m) * 64 + q * 8)
                                      : (W2h + (n * 64 + m - 64) * 64 + q * 8);
        cp16(Bb + sw_off(m, q), wsrc, 16);
    }
    CP_COMMIT();
    CP_WAIT0();
    __syncthreads();

    float acc[2][8][4];
#pragma unroll
    for (int a = 0; a < 2; a++)
#pragma unroll
        for (int b = 0; b < 8; b++)
#pragma unroll
            for (int c = 0; c < 4; c++) acc[a][b][c] = 0.f;

    const int a_row = lane & 15, a_kh = lane >> 4;
    const int b_row = (lane & 7) + ((lane >> 4) & 1) * 8;
    const int b_kh = (lane >> 3) & 1;

#pragma unroll
    for (int ks = 0; ks < 4; ks++) {
        unsigned af[2][4], bf[8][2];
#pragma unroll
        for (int mi = 0; mi < 2; mi++) {
            int row = wm + mi * 16 + a_row;
            ldsm_x4(af[mi][0], af[mi][1], af[mi][2], af[mi][3],
                    Ab + sw_off(row, 0) + ((((ks * 2 + a_kh) ^ (row & 7)) ^ (0 ^ (row & 7))) << 4));
        }
        // note: sw_off(row,0) already xors 0^(row&7); recompute cleanly:
#pragma unroll
        for (int mi = 0; mi < 2; mi++) {
            int row = wm + mi * 16 + a_row;
            ldsm_x4(af[mi][0], af[mi][1], af[mi][2], af[mi][3],
                    Ab + (uint32_t)(row * 128 + (((ks * 2 + a_kh) ^ l7) << 4)));
        }
#pragma unroll
        for (int njp = 0; njp < 4; njp++) {
            int row = wn + njp * 16 + b_row;
            ldsm_x4(bf[2 * njp][0], bf[2 * njp][1], bf[2 * njp + 1][0], bf[2 * njp + 1][1],
                    Bb + (uint32_t)(row * 128 + (((ks * 2 + b_kh) ^ l7) << 4)));
        }
#pragma unroll
        for (int mi = 0; mi < 2; mi++)
#pragma unroll
            for (int nj = 0; nj < 8; nj++) MMA_F16(acc[mi][nj], af[mi], bf[nj]);
    }

    float* outp = (wn == 0) ? h : ud;
#pragma unroll
    for (int mi = 0; mi < 2; mi++) {
#pragma unroll
        for (int nj = 0; nj < 8; nj++) {
            int col = n * 64 + nj * 8 + (kc << 1);
            size_t r0 = (size_t)(t0 + wm + mi * 16 + rr);
            *(float2*)(outp + r0 * DD + col) =
                make_float2(silu_f(acc[mi][nj][0]), silu_f(acc[mi][nj][1]));
            *(float2*)(outp + (r0 + 8) * DD + col) =
                make_float2(silu_f(acc[mi][nj][2]), silu_f(acc[mi][nj][3]));
        }
    }
}

// ======== bd192: r = silu(concat @ wpost^T), virtual concat, fp16 out. M=128,N=64,K=192 ===
#define BD192_SMEM (3 * 16384 + 3 * 8192)  // 73728
__global__ void __launch_bounds__(256)
bd192_f16_kernel(const __half* __restrict__ hn, const __half* __restrict__ eh,
                 const __half* __restrict__ Wh, __half* __restrict__ rh) {
    extern __shared__ __align__(16) char smc[];
    const uint32_t Ab = smem_u32(smc);                 // 3 chunks of [128][64h]
    const uint32_t Bb = Ab + 3 * 16384;                // 3 chunks of [64][64h]
    const int t0 = blockIdx.x * 128;
    const int n = blockIdx.y;
    const int tid = threadIdx.x;
    const int lane = tid & 31;
    const int warp = tid >> 5;
    const int wm = (warp >> 1) * 32;
    const int wn = (warp & 1) * 32;
    const int rr = lane >> 2, kc = lane & 3, l7 = lane & 7;

#pragma unroll
    for (int c = 0; c < 3; c++) {
        const int pc = 3 * n + c;
        const int part = pc >> 4;
        const int colo = (pc & 15) << 6;
#pragma unroll
        for (int i = 0; i < 4; i++) {
            int cch = tid + i * 256;
            int m = cch >> 3, q = cch & 7;
            int trow = t0 + m;
            uint32_t dst = Ab + c * 16384 + sw_off(m, q);
            if (part == 0) {
                cp16(dst, hn + (size_t)trow * DD + colo + q * 8, 16);
            } else if (part == 1) {
                cp16(dst, eh + (size_t)trow * DD + colo + q * 8, 16);
            } else {
                const __half* src = eh + (size_t)(trow - 1) * DD + colo + q * 8;
                cp16(dst, (trow == 0) ? (const __half*)eh : src, (trow == 0) ? 0 : 16);
            }
        }
#pragma unroll
        for (int i = 0; i < 2; i++) {
            int cch = tid + i * 256;
            int o = cch >> 3, q = cch & 7;
            cp16(Bb + c * 8192 + sw_off(o, q), Wh + (size_t)(n * 64 + o) * 192 + c * 64 + q * 8, 16);
        }
    }
    CP_COMMIT();
    CP_WAIT0();
    __syncthreads();

    float acc[2][4][4];
#pragma unroll
    for (int a = 0; a < 2; a++)
#pragma unroll
        for (int b = 0; b < 4; b++)
#pragma unroll
            for (int c = 0; c < 4; c++) acc[a][b][c] = 0.f;

    const int a_row = lane & 15, a_kh = lane >> 4;
    const int b_row = (lane & 7) + ((lane >> 4) & 1) * 8;
    const int b_kh = (lane >> 3) & 1;

#pragma unroll
    for (int ks = 0; ks < 12; ks++) {
        const int c = ks >> 2, ksl = ks & 3;
        unsigned af[2][4], bf[4][2];
#pragma unroll
        for (int mi = 0; mi < 2; mi++) {
            int row = wm + mi * 16 + a_row;
            ldsm_x4(af[mi][0], af[mi][1], af[mi][2], af[mi][3],
                    Ab + c * 16384 + (uint32_t)(row * 128 + (((ksl * 2 + a_kh) ^ l7) << 4)));
        }
#pragma unroll
        for (int njp = 0; njp < 2; njp++) {
            int row = wn + njp * 16 + b_row;
            ldsm_x4(bf[2 * njp][0], bf[2 * njp][1], bf[2 * njp + 1][0], bf[2 * njp + 1][1],
                    Bb + c * 8192 + (uint32_t)(row * 128 + (((ksl * 2 + b_kh) ^ l7) << 4)));
        }
#pragma unroll
        for (int mi = 0; mi < 2; mi++)
#pragma unroll
            for (int nj = 0; nj < 4; nj++) MMA_F16(acc[mi][nj], af[mi], bf[nj]);
    }

#pragma unroll
    for (int mi = 0; mi < 2; mi++) {
#pragma unroll
        for (int nj = 0; nj < 4; nj++) {
            int col = n * 64 + wn + nj * 8 + (kc << 1);
            size_t r0 = (size_t)(t0 + wm + mi * 16 + rr);
            *(__half2*)(rh + r0 * HH + col) =
                __floats2half2_rn(silu_f(acc[mi][nj][0]), silu_f(acc[mi][nj][1]));
            *(__half2*)(rh + (r0 + 8) * HH + col) =
                __floats2half2_rn(silu_f(acc[mi][nj][2]), silu_f(acc[mi][nj][3]));
        }
    }
}

// ======== update: x += rh@wlocal^T + tmp@lowA^T. M=128, N=64, K=64+64 ========
__global__ void __launch_bounds__(256)
update_f16_kernel(float* __restrict__ x, const __half* __restrict__ rh,
                  const __half* __restrict__ tmph, const __half* __restrict__ wloc,
                  const __half* __restrict__ lowA) {
    __shared__ __half Ash[2][128 * 64];
    __shared__ __half Bsh[2][64 * 64];
    const int t0 = blockIdx.x * 128;
    const int n = blockIdx.y;
    const int tid = threadIdx.x;
    const int lane = tid & 31;
    const int warp = tid >> 5;
    const uint32_t Ab0 = smem_u32(Ash[0]), Ab1 = smem_u32(Ash[1]);
    const uint32_t Bb0 = smem_u32(Bsh[0]), Bb1 = smem_u32(Bsh[1]);
    const int wm = (warp >> 1) * 32;
    const int wn = (warp & 1) * 32;
    const int rr = lane >> 2, kc = lane & 3, l7 = lane & 7;

#pragma unroll
    for (int i = 0; i < 4; i++) {
        int cch = tid + i * 256;
        int m = cch >> 3, q = cch & 7;
        cp16(Ab0 + sw_off(m, q), rh + (size_t)(t0 + m) * HH + n * 64 + q * 8, 16);
        cp16(Ab1 + sw_off(m, q), tmph + (size_t)(t0 + m) * RANKK + q * 8, 16);
    }
#pragma unroll
    for (int i = 0; i < 2; i++) {
        int cch = tid + i * 256;
        int o = cch >> 3, q = cch & 7;
        cp16(Bb0 + sw_off(o, q), wloc + (size_t)(n * 64 + o) * 64 + q * 8, 16);
        cp16(Bb1 + sw_off(o, q), lowA + (size_t)(n * 64 + o) * RANKK + q * 8, 16);
    }
    CP_COMMIT();
    CP_WAIT0();
    __syncthreads();

    float acc[2][4][4];
#pragma unroll
    for (int a = 0; a < 2; a++)
#pragma unroll
        for (int b = 0; b < 4; b++)
#pragma unroll
            for (int c = 0; c < 4; c++) acc[a][b][c] = 0.f;

    const int a_row = lane & 15, a_kh = lane >> 4;
    const int b_row = (lane & 7) + ((lane >> 4) & 1) * 8;
    const int b_kh = (lane >> 3) & 1;

#pragma unroll
    for (int ks = 0; ks < 8; ks++) {
        const int ph = ks >> 2, ksl = ks & 3;
        const uint32_t Ab = ph ? Ab1 : Ab0;
        const uint32_t Bb = ph ? Bb1 : Bb0;
        unsigned af[2][4], bf[4][2];
#pragma unroll
        for (int mi = 0; mi < 2; mi++) {
            int row = wm + mi * 16 + a_row;
            ldsm_x4(af[mi][0], af[mi][1], af[mi][2], af[mi][3],
                    Ab + (uint32_t)(row * 128 + (((ksl * 2 + a_kh) ^ l7) << 4)));
        }
#pragma unroll
        for (int njp = 0; njp < 2; njp++) {
            int row = wn + njp * 16 + b_row;
            ldsm_x4(bf[2 * njp][0], bf[2 * njp][1], bf[2 * njp + 1][0], bf[2 * njp + 1][1],
                    Bb + (uint32_t)(row * 128 + (((ksl * 2 + b_kh) ^ l7) << 4)));
        }
#pragma unroll
        for (int mi = 0; mi < 2; mi++)
#pragma unroll
            for (int nj = 0; nj < 4; nj++) MMA_F16(acc[mi][nj], af[mi], bf[nj]);
    }

#pragma unroll
    for (int mi = 0; mi < 2; mi++) {
#pragma unroll
        for (int nj = 0; nj < 4; nj++) {
            int col = n * 64 + wn + nj * 8 + (kc << 1);
            size_t r0 = (size_t)(t0 + wm + mi * 16 + rr);
            float2* p0 = (float2*)(x + r0 * DD + col);
            float2 v0 = *p0;
            v0.x += acc[mi][nj][0]; v0.y += acc[mi][nj][1];
            *p0 = v0;
            float2* p1 = (float2*)(x + (r0 + 8) * DD + col);
            float2 v1 = *p1;
            v1.x += acc[mi][nj][2]; v1.y += acc[mi][nj][3];
            *p1 = v1;
        }
    }
}

// ======== lowrank1: tmp = rh @ lowB^T. M=64/block, N=64, K=1024, 2-stage ========
__global__ void __launch_bounds__(256)
lowrank1_f16_kernel(const __half* __restrict__ rh, const __half* __restrict__ lowB,
                    __half* __restrict__ tmph) {
    __shared__ __half Ash[2][64 * 64];
    __shared__ __half Bsh[2][64 * 64];
    const int t0 = blockIdx.x * 64;
    const int tid = threadIdx.x;
    const int lane = tid & 31;
    const int warp = tid >> 5;
    const int wm = (warp >> 2) * 32;
    const int wn = (warp & 3) * 16;
    const int rr = lane >> 2, kc = lane & 3, l7 = lane & 7;

#define LR_LOAD(s, kb)                                                                   \
    {                                                                                    \
        _Pragma("unroll") for (int i = 0; i < 2; i++) {                                  \
            int cch = tid + i * 256;                                                     \
            int m = cch >> 3, q = cch & 7;                                               \
            cp16(smem_u32(Ash[s]) + sw_off(m, q),                                        \
                 rh + (size_t)(t0 + m) * HH + (kb) * 64 + q * 8, 16);                    \
            cp16(smem_u32(Bsh[s]) + sw_off(m, q),                                        \
                 lowB + (size_t)m * HH + (kb) * 64 + q * 8, 16);                         \
        }                                                                                \
        CP_COMMIT();                                                                     \
    }

    float acc[2][2][4];
#pragma unroll
    for (int a = 0; a < 2; a++)
#pragma unroll
        for (int b = 0; b < 2; b++)
#pragma unroll
            for (int c = 0; c < 4; c++) acc[a][b][c] = 0.f;

    const int a_row = lane & 15, a_kh = lane >> 4;
    const int b_row = (lane & 7) + ((lane >> 4) & 1) * 8;
    const int b_kh = (lane >> 3) & 1;

    LR_LOAD(0, 0);
    for (int kb = 0; kb < 16; kb++) {
        const int s = kb & 1;
        if (kb + 1 < 16) {
            LR_LOAD(s ^ 1, kb + 1);
            asm volatile("cp.async.wait_group 1;" ::: "memory");
        } else {
            CP_WAIT0();
        }
        __syncthreads();
        const uint32_t Ab = smem_u32(Ash[s]);
        const uint32_t Bb = smem_u32(Bsh[s]);
#pragma unroll
        for (int ks = 0; ks < 4; ks++) {
            unsigned af[2][4], bf[2][2];
#pragma unroll
            for (int mi = 0; mi < 2; mi++) {
                int row = wm + mi * 16 + a_row;
                ldsm_x4(af[mi][0], af[mi][1], af[mi][2], af[mi][3],
                        Ab + (uint32_t)(row * 128 + (((ks * 2 + a_kh) ^ l7) << 4)));
            }
            {
                int row = wn + b_row;
                ldsm_x4(bf[0][0], bf[0][1], bf[1][0], bf[1][1],
                        Bb + (uint32_t)(row * 128 + (((ks * 2 + b_kh) ^ l7) << 4)));
            }
#pragma unroll
            for (int mi = 0; mi < 2; mi++)
#pragma unroll
                for (int nj = 0; nj < 2; nj++) MMA_F16(acc[mi][nj], af[mi], bf[nj]);
        }
        __syncthreads();
    }

#pragma unroll
    for (int mi = 0; mi < 2; mi++) {
#pragma unroll
        for (int nj = 0; nj < 2; nj++) {
            int col = wn + nj * 8 + (kc << 1);
            size_t r0 = (size_t)(t0 + wm + mi * 16 + rr);
            *(__half2*)(tmph + r0 * RANKK + col) =
                __floats2half2_rn(acc[mi][nj][0], acc[mi][nj][1]);
            *(__half2*)(tmph + (r0 + 8) * RANKK + col) =
                __floats2half2_rn(acc[mi][nj][2], acc[mi][nj][3]);
        }
    }
}

// ============ causal scan, 3-phase chunked (fp32, exact) ============
__global__ void scanA_kernel(float* __restrict__ buf, const float* __restrict__ logA,
                             const float* __restrict__ logdt, float* __restrict__ seg) {
    int d = blockIdx.x * 32 + threadIdx.x;
    int s = blockIdx.y * 8 + threadIdx.y;
    float a = expf(-expf(logA[d]) * expf(logdt[d]));
    float y = 0.f;
    int t0 = s * SEGLEN;
#pragma unroll 8
    for (int tt = 0; tt < SEGLEN; tt++) {
        int i = (t0 + tt) * DD + d;
        y = a * y + buf[i];
        buf[i] = y;
    }
    seg[s * DD + d] = y;
}

__global__ void scanB_kernel(float* __restrict__ seg, const float* __restrict__ logA,
                             const float* __restrict__ logdt) {
    int d = blockIdx.x * 16 + threadIdx.x;
    int j = threadIdx.y;
    float a = expf(-expf(logA[d]) * expf(logdt[d]));
    float a32 = a;
#pragma unroll
    for (int q = 0; q < 5; q++) a32 *= a32;
    __shared__ float s[NSEG][17];
    float cur = seg[j * DD + d];
    s[j][threadIdx.x] = cur;
    float m = a32;
    for (int st = 1; st < NSEG; st <<= 1) {
        __syncthreads();
        float prev = (j >= st) ? s[j - st][threadIdx.x] : 0.f;
        __syncthreads();
        cur += m * prev;
        s[j][threadIdx.x] = cur;
        m = m * m;
    }
    seg[j * DD + d] = cur;
}

__global__ void scanC_kernel(float* __restrict__ buf, const float* __restrict__ logA,
                             const float* __restrict__ logdt, const float* __restrict__ seg) {
    int d = blockIdx.x * 32 + threadIdx.x;
    int s = blockIdx.y * 8 + threadIdx.y;
    if (s == 0) return;
    float a = expf(-expf(logA[d]) * expf(logdt[d]));
    float carry = seg[(s - 1) * DD + d];
    float f = a;
    int t0 = s * SEGLEN;
#pragma unroll 8
    for (int tt = 0; tt < SEGLEN; tt++) {
        int i = (t0 + tt) * DD + d;
        buf[i] += f * carry;
        f *= a;
    }
}

// ---------------- combine: hn = rmsnorm(hseq + gain*ud) -> fp16 ----------------
__global__ void combine_kernel(const float* __restrict__ h, const float* __restrict__ udep,
                               const float* __restrict__ logAd, const float* __restrict__ logdtd,
                               const int* __restrict__ pK, __half* __restrict__ hn) {
    int t = blockIdx.x;
    int tid = threadIdx.x;
    int K = *pK;
    float hv[4];
    float ss = 0.f;
#pragma unroll
    for (int r = 0; r < 4; r++) {
        int d = tid + r * 256;
        float g;
        if (d < NMEM) {
            g = (float)K;
        } else {
            float aD = expf(-expf(logAd[d - NMEM]) * expf(logdtd[d - NMEM]));
            float om = 1.f - aD;
            float safe = fmaxf(om, 1e-8f);
            float p = 1.f;
            for (int k = 0; k < K; k++) p *= aD;
            g = (fabsf(om) < 1e-6f) ? (float)K : (1.f - p) / safe;
        }
        float hx = h[t * DD + d] + g * udep[t * DD + d];
        hv[r] = hx;
        ss += hx * hx;
    }
    __shared__ float red[256];
    red[tid] = ss;
    __syncthreads();
    for (int s = 128; s > 0; s >>= 1) {
        if (tid < s) red[tid] += red[tid + s];
        __syncthreads();
    }
    float sc = rsqrtf(red[0] / (float)DD + RMS_EPS);
#pragma unroll
    for (int r = 0; r < 4; r++) {
        int d = tid + r * 256;
        hn[t * DD + d] = __float2half_rn(hv[r] * sc);
    }
}

// ================= LM head GEMM (fp16 m16n8k16, ldmatrix + SW128, 4-stage) =====
#define A_ST 16384
#define B_ST 32768
#define NSTG 4
#define LM_SMEM (NSTG * (A_ST + B_ST))

__global__ void __launch_bounds__(256, 1)
lmhead_gemm(const __half* __restrict__ A, const __half* __restrict__ B, float* __restrict__ C) {
    extern __shared__ __align__(16) char smc[];
    const uint32_t smb = smem_u32(smc);
    const int tid = threadIdx.x;
    const int lane = tid & 31;
    const int warp = tid >> 5;
    const int M0 = blockIdx.x * 128;
    const int N0 = blockIdx.y * 256;
    const int nVal = (VV - N0 < 256) ? (VV - N0) : 256;
    const int wm = (warp >> 2) * 64;
    const int wn = (warp & 3) * 64;
    const int rr = lane >> 2;
    const int kc = lane & 3;
    const int l7 = lane & 7;

    float acc[4][8][4];
#pragma unroll
    for (int i = 0; i < 4; i++)
#pragma unroll
        for (int j = 0; j < 8; j++)
#pragma unroll
            for (int k = 0; k < 4; k++) acc[i][j][k] = 0.f;

#define LOAD_STAGE(s, kb)                                                              \
    {                                                                                  \
        _Pragma("unroll") for (int i = 0; i < 4; i++) {                                \
            int cch = tid + i * 256;                                                   \
            int m = cch >> 3, q = cch & 7;                                             \
            uint32_t dst = smb + (s) * A_ST + (uint32_t)(m * 128 + ((q ^ (m & 7)) << 4));\
            const __half* src = A + (size_t)(M0 + m) * DD + (kb) * 64 + q * 8;         \
            cp16(dst, src, 16);                                                        \
        }                                                                              \
        _Pragma("unroll") for (int i = 0; i < 8; i++) {                                \
            int cch = tid + i * 256;                                                   \
            int n = cch >> 3, q = cch & 7;                                             \
            uint32_t dst = smb + NSTG * A_ST + (s) * B_ST +                            \
                           (uint32_t)(n * 128 + ((q ^ (n & 7)) << 4));                 \
            int ok = (n < nVal);                                                       \
            const __half* src = B + (size_t)(N0 + (ok ? n : 0)) * DD + (kb) * 64 + q * 8;\
            cp16(dst, src, ok ? 16 : 0);                                               \
        }                                                                              \
        CP_COMMIT();                                                                   \
    }

    LOAD_STAGE(0, 0);
    LOAD_STAGE(1, 1);
    LOAD_STAGE(2, 2);

    const int a_row = (lane & 15);
    const int a_kh = lane >> 4;
    const int b_row = (lane & 7) + ((lane >> 4) & 1) * 8;
    const int b_kh = (lane >> 3) & 1;

    const int NKB = DD / 64;
    for (int kb = 0; kb < NKB; kb++) {
        const int s = kb & 3;
        if (kb < NKB - 2) {
            asm volatile("cp.async.wait_group 2;" ::: "memory");
        } else if (kb == NKB - 2) {
            asm volatile("cp.async.wait_group 1;" ::: "memory");
        } else {
            asm volatile("cp.async.wait_group 0;" ::: "memory");
        }
        __syncthreads();
        if (kb + 3 < NKB) LOAD_STAGE((kb + 3) & 3, kb + 3);

        const uint32_t Ab = smb + s * A_ST;
        const uint32_t Bb = smb + NSTG * A_ST + s * B_ST;

#pragma unroll
        for (int ks = 0; ks < 4; ks++) {
            unsigned af[4][4], bf[8][2];
#pragma unroll
            for (int mi = 0; mi < 4; mi++) {
                int row = wm + mi * 16 + a_row;
                int chunk = (ks * 2 + a_kh) ^ l7;
                ldsm_x4(af[mi][0], af[mi][1], af[mi][2], af[mi][3],
                        Ab + (uint32_t)(row * 128 + (chunk << 4)));
            }
#pragma unroll
            for (int njp = 0; njp < 4; njp++) {
                int row = wn + njp * 16 + b_row;
                int chunk = (ks * 2 + b_kh) ^ l7;
                ldsm_x4(bf[2 * njp][0], bf[2 * njp][1], bf[2 * njp + 1][0], bf[2 * njp + 1][1],
                        Bb + (uint32_t)(row * 128 + (chunk << 4)));
            }
#pragma unroll
            for (int mi = 0; mi < 4; mi++)
#pragma unroll
                for (int nj = 0; nj < 8; nj++) MMA_F16(acc[mi][nj], af[mi], bf[nj]);
        }
    }

#pragma unroll
    for (int mi = 0; mi < 4; mi++) {
#pragma unroll
        for (int nj = 0; nj < 8; nj++) {
            int c0 = N0 + wn + nj * 8 + (kc << 1);
            if (c0 < VV) {
                size_t r0 = (size_t)(M0 + wm + mi * 16 + rr);
                *(float2*)(C + r0 * VV + c0) =
                    make_float2(acc[mi][nj][0] * BSCALE_INV, acc[mi][nj][1] * BSCALE_INV);
                *(float2*)(C + (r0 + 8) * VV + c0) =
                    make_float2(acc[mi][nj][2] * BSCALE_INV, acc[mi][nj][3] * BSCALE_INV);
            }
        }
    }
}

// ---------------- launcher ----------------
extern "C" void kernel_launch(void* const* d_in, const int* in_sizes, int n_in,
                              void* d_out, int out_size) {
    const int* idx = (const int*)d_in[0];
    const int* pK = (const int*)d_in[1];
    const float* wte = (const float*)d_in[2];
    const float* wpe = (const float*)d_in[3];
    const float* bseq_w = (const float*)d_in[4];
    const float* logA_seq = (const float*)d_in[5];
    const float* logdt_seq = (const float*)d_in[6];
    const float* bdepth_w = (const float*)d_in[7];
    const float* logA_depth = (const float*)d_in[8];
    const float* logdt_depth = (const float*)d_in[9];
    const float* wpost_w = (const float*)d_in[10];
    const float* wlocal_w = (const float*)d_in[11];
    const float* lowA = (const float*)d_in[12];
    const float* lowB = (const float*)d_in[13];
    const float* lm_head_w = (const float*)d_in[14];
    float* out = (float*)d_out;

    float *x, *h, *ud, *seg;
    __half *eh, *hn, *rh, *tmph, *xh, *Bh;
    __half *bseqh, *bdeph, *wposth, *wloch, *lowAh, *lowBh;
    cudaGetSymbolAddress((void**)&x, g_x);
    cudaGetSymbolAddress((void**)&h, g_h);
    cudaGetSymbolAddress((void**)&ud, g_ud);
    cudaGetSymbolAddress((void**)&seg, g_seg);
    cudaGetSymbolAddress((void**)&eh, g_eh);
    cudaGetSymbolAddress((void**)&hn, g_hn);
    cudaGetSymbolAddress((void**)&rh, g_rh);
    cudaGetSymbolAddress((void**)&tmph, g_tmph);
    cudaGetSymbolAddress((void**)&xh, g_xh);
    cudaGetSymbolAddress((void**)&Bh, g_Bh);
    cudaGetSymbolAddress((void**)&bseqh, g_bseqh);
    cudaGetSymbolAddress((void**)&bdeph, g_bdeph);
    cudaGetSymbolAddress((void**)&wposth, g_wposth);
    cudaGetSymbolAddress((void**)&wloch, g_wloch);
    cudaGetSymbolAddress((void**)&lowAh, g_lowAh);
    cudaGetSymbolAddress((void**)&lowBh, g_lowBh);

    cudaFuncSetAttribute(lmhead_gemm, cudaFuncAttributeMaxDynamicSharedMemorySize, LM_SMEM);
    cudaFuncSetAttribute(bd192_f16_kernel, cudaFuncAttributeMaxDynamicSharedMemorySize, BD192_SMEM);

    // weight conversions
    f16_convert_kernel<<<(VV * DD / 8) / 256, 256>>>(lm_head_w, Bh);
    conv_f16_kernel<<<LYR * NBLK * 64 * 64 / 8 / 256, 256>>>(bseq_w, bseqh);
    conv_f16_kernel<<<LYR * NBLK * 64 * 64 / 8 / 256, 256>>>(bdepth_w, bdeph);
    conv_f16_kernel<<<LYR * NBLK * 64 * 192 / 8 / 256, 256>>>(wpost_w, wposth);
    conv_f16_kernel<<<LYR * NBLK * 64 * 64 / 8 / 256, 256>>>(wlocal_w, wloch);
    conv_f16_kernel<<<LYR * DD * RANKK / 8 / 256, 256>>>(lowA, lowAh);
    conv_f16_kernel<<<LYR * RANKK * HH / 8 / 256, 256>>>(lowB, lowBh);

    embed_kernel<<<TT, 256>>>(idx, wte, wpe, x);

    for (int l = 0; l < LYR; l++) {
        const __half* bseq_l = bseqh + l * NBLK * 64 * 64;
        const __half* bdep_l = bdeph + l * NBLK * 64 * 64;
        const __half* wpost_l = wposth + l * NBLK * 64 * 192;
        const __half* wlocal_l = wloch + l * NBLK * 64 * 64;
        const __half* lowA_l = lowAh + l * DD * RANKK;
        const __half* lowB_l = lowBh + l * RANKK * HH;
        const float* lAs = logA_seq + l * HH;
        const float* lDs = logdt_seq + l * HH;
        const float* lAd = logA_depth + l * (HH - NMEM);
        const float* lDd = logdt_depth + l * (HH - NMEM);

        rmsnorm_f16_kernel<<<TT, 256>>>(x, eh);
        bd64_f16_kernel<<<dim3(TT / 128, NBLK), 256>>>(eh, bseq_l, bdep_l, h, ud);
        scanA_kernel<<<dim3(32, 8), dim3(32, 8)>>>(h, lAs, lDs, seg);
        scanB_kernel<<<DD / 16, dim3(16, NSEG)>>>(seg, lAs, lDs);
        scanC_kernel<<<dim3(32, 8), dim3(32, 8)>>>(h, lAs, lDs, seg);
        combine_kernel<<<TT, 256>>>(h, ud, lAd, lDd, pK, hn);
        bd192_f16_kernel<<<dim3(TT / 128, NBLK), 256, BD192_SMEM>>>(hn, eh, wpost_l, rh);
        lowrank1_f16_kernel<<<TT / 64, 256>>>(rh, lowB_l, tmph);
        update_f16_kernel<<<dim3(TT / 128, NBLK), 256>>>(x, rh, tmph, wlocal_l, lowA_l);
    }

    rmsnorm_f16_kernel<<<TT, 256>>>(x, xh);
    lmhead_gemm<<<dim3(TT / 128, (VV + 255) / 256), 256, LM_SMEM>>>(xh, Bh, out);
}

// round 15
// speedup vs baseline: 1.5733x; 1.0108x over previous
#include <cuda_runtime.h>
#include <cuda_bf16.h>
#include <cuda_fp16.h>
#include <math.h>
#include <stdint.h>

#define TT 2048
#define DD 1024
#define HH 1024
#define NBLK 16
#define LYR 4
#define RANKK 64
#define NMEM 64
#define VV 50304
#define RMS_EPS 1.1920929e-7f
#define SEGLEN 32
#define NSEG 64
#define BSCALE 1024.0f
#define BSCALE_INV 0.0009765625f

// ---------------- scratch ----------------
__device__ float g_x[TT * DD];
__device__ float g_h[TT * DD];
__device__ float g_ud[TT * DD];
__device__ float g_seg[NSEG * DD];
__device__ __half g_eh[TT * DD];
__device__ __half g_hn[TT * DD];
__device__ __half g_rh[TT * HH];
__device__ __half g_tmph[TT * RANKK];
__device__ __half g_xh[TT * DD];
__device__ __half g_Bh[(size_t)VV * DD];
__device__ __half g_bseqh[LYR * NBLK * 64 * 64];
__device__ __half g_bdeph[LYR * NBLK * 64 * 64];
__device__ __half g_wposth[LYR * NBLK * 64 * 192];
__device__ __half g_wloch[LYR * NBLK * 64 * 64];
__device__ __half g_lowAh[LYR * DD * RANKK];
__device__ __half g_lowBh[LYR * RANKK * HH];

// ---------------- helpers ----------------
__device__ __forceinline__ float silu_f(float x) { return x / (1.0f + expf(-x)); }

__device__ __forceinline__ uint32_t smem_u32(const void* p) {
    uint32_t a;
    asm("{ .reg .u64 t; cvta.to.shared.u64 t, %1; cvt.u32.u64 %0, t; }" : "=r"(a) : "l"(p));
    return a;
}
__device__ __forceinline__ void cp16(uint32_t dst, const void* src, int sz) {
    asm volatile("cp.async.cg.shared.global [%0], [%1], 16, %2;"
                 :: "r"(dst), "l"(src), "r"(sz) : "memory");
}
#define CP_COMMIT() asm volatile("cp.async.commit_group;" ::: "memory")
#define CP_WAIT0() asm volatile("cp.async.wait_group 0;" ::: "memory")

__device__ __forceinline__ void ldsm_x4(unsigned& r0, unsigned& r1, unsigned& r2, unsigned& r3,
                                        uint32_t addr) {
    asm volatile("ldmatrix.sync.aligned.m8n8.x4.shared.b16 {%0,%1,%2,%3}, [%4];"
                 : "=r"(r0), "=r"(r1), "=r"(r2), "=r"(r3) : "r"(addr));
}

#define MMA_F16(c, a, b)                                                               \
    asm volatile(                                                                      \
        "mma.sync.aligned.m16n8k16.row.col.f32.f16.f16.f32 "                           \
        "{%0,%1,%2,%3},{%4,%5,%6,%7},{%8,%9},{%0,%1,%2,%3};\n"                         \
        : "+f"(c[0]), "+f"(c[1]), "+f"(c[2]), "+f"(c[3])                               \
        : "r"(a[0]), "r"(a[1]), "r"(a[2]), "r"(a[3]), "r"(b[0]), "r"(b[1]))

__device__ __forceinline__ uint32_t sw_off(int row, int q) {
    return (uint32_t)(row * 128 + ((q ^ (row & 7)) << 4));
}

// ---------------- embedding ----------------
__global__ void embed_kernel(const int* __restrict__ idx, const float* __restrict__ wte,
                             const float* __restrict__ wpe, float* __restrict__ x) {
    int t = blockIdx.x;
    int row = idx[t];
    const float4* wrow = (const float4*)(wte + (long)row * DD);
    const float4* prow = (const float4*)(wpe + (long)t * DD);
    float4* xo = (float4*)(x + t * DD);
    for (int d = threadIdx.x; d < DD / 4; d += blockDim.x) {
        float4 a = wrow[d], b = prow[d];
        xo[d] = make_float4(a.x + b.x, a.y + b.y, a.z + b.z, a.w + b.w);
    }
}

// ---------------- rmsnorm -> fp16 ----------------
__global__ void rmsnorm_f16_kernel(const float* __restrict__ in, __half* __restrict__ out) {
    int t = blockIdx.x;
    int tid = threadIdx.x;
    float4 v = ((const float4*)(in + t * DD))[tid];
    float ss = v.x * v.x + v.y * v.y + v.z * v.z + v.w * v.w;
    __shared__ float red[256];
    red[tid] = ss;
    __syncthreads();
    for (int s = 128; s > 0; s >>= 1) {
        if (tid < s) red[tid] += red[tid + s];
        __syncthreads();
    }
    float sc = rsqrtf(red[0] / (float)DD + RMS_EPS);
    __half2 h0 = __floats2half2_rn(v.x * sc, v.y * sc);
    __half2 h1 = __floats2half2_rn(v.z * sc, v.w * sc);
    ((__half2*)(out + t * DD))[tid * 2] = h0;
    ((__half2*)(out + t * DD))[tid * 2 + 1] = h1;
}

// lm_head weights: *1024, fp16
__global__ void f16_convert_kernel(const float* __restrict__ in, __half* __restrict__ out) {
    size_t i = (size_t)blockIdx.x * blockDim.x + threadIdx.x;
    const float4* in4 = (const float4*)in + i * 2;
    float4 a = in4[0], b = in4[1];
    __half h[8];
    h[0] = __float2half_rn(a.x * BSCALE); h[1] = __float2half_rn(a.y * BSCALE);
    h[2] = __float2half_rn(a.z * BSCALE); h[3] = __float2half_rn(a.w * BSCALE);
    h[4] = __float2half_rn(b.x * BSCALE); h[5] = __float2half_rn(b.y * BSCALE);
    h[6] = __float2half_rn(b.z * BSCALE); h[7] = __float2half_rn(b.w * BSCALE);
    ((uint4*)(out + i * 8))[0] = *(uint4*)&h[0];
}

// convert 5 equal-size fp32 arrays -> fp16 (blockIdx.y selects array)
__global__ void conv5_f16_kernel(const float* __restrict__ p0, __half* __restrict__ q0,
                                 const float* __restrict__ p1, __half* __restrict__ q1,
                                 const float* __restrict__ p2, __half* __restrict__ q2,
                                 const float* __restrict__ p3, __half* __restrict__ q3,
                                 const float* __restrict__ p4, __half* __restrict__ q4) {
    const float* in;
    __half* out;
    switch (blockIdx.y) {
        case 0: in = p0; out = q0; break;
        case 1: in = p1; out = q1; break;
        case 2: in = p2; out = q2; break;
        case 3: in = p3; out = q3; break;
        default: in = p4; out = q4; break;
    }
    size_t i = (size_t)blockIdx.x * blockDim.x + threadIdx.x;
    const float4* in4 = (const float4*)in + i * 2;
    float4 a = in4[0], b = in4[1];
    __half h[8];
    h[0] = __float2half_rn(a.x); h[1] = __float2half_rn(a.y);
    h[2] = __float2half_rn(a.z); h[3] = __float2half_rn(a.w);
    h[4] = __float2half_rn(b.x); h[5] = __float2half_rn(b.y);
    h[6] = __float2half_rn(b.z); h[7] = __float2half_rn(b.w);
    ((uint4*)(out + i * 8))[0] = *(uint4*)&h[0];
}

__global__ void conv_f16_kernel(const float* __restrict__ in, __half* __restrict__ out) {
    size_t i = (size_t)blockIdx.x * blockDim.x + threadIdx.x;
    const float4* in4 = (const float4*)in + i * 2;
    float4 a = in4[0], b = in4[1];
    __half h[8];
    h[0] = __float2half_rn(a.x); h[1] = __float2half_rn(a.y);
    h[2] = __float2half_rn(a.z); h[3] = __float2half_rn(a.w);
    h[4] = __float2half_rn(b.x); h[5] = __float2half_rn(b.y);
    h[6] = __float2half_rn(b.z); h[7] = __float2half_rn(b.w);
    ((uint4*)(out + i * 8))[0] = *(uint4*)&h[0];
}

// ======== bd64 dual: h=silu(e@W1^T), ud=silu(e@W2^T). M=128, N=128(W1|W2), K=64 =========
__global__ void __launch_bounds__(256)
bd64_f16_kernel(const __half* __restrict__ eh, const __half* __restrict__ W1h,
                const __half* __restrict__ W2h, float* __restrict__ h, float* __restrict__ ud) {
    __shared__ __half Ash[128 * 64];
    __shared__ __half Bsh[128 * 64];
    const int t0 = blockIdx.x * 128;
    const int n = blockIdx.y;
    const int tid = threadIdx.x;
    const int lane = tid & 31;
    const int warp = tid >> 5;
    const uint32_t Ab = smem_u32(Ash), Bb = smem_u32(Bsh);
    const int wm = (warp >> 1) * 32;
    const int wn = (warp & 1) * 64;
    const int rr = lane >> 2, kc = lane & 3, l7 = lane & 7;

#pragma unroll
    for (int i = 0; i < 4; i++) {
        int cch = tid + i * 256;
        int m = cch >> 3, q = cch & 7;
        cp16(Ab + sw_off(m, q), eh + (size_t)(t0 + m) * DD + n * 64 + q * 8, 16);
        const __half* wsrc = (m < 64) ? (W1h + (n * 64 + m) * 64 + q * 8)
                                      : (W2h + (n * 64 + m - 64) * 64 + q * 8);
        cp16(Bb + sw_off(m, q), wsrc, 16);
    }
    CP_COMMIT();
    CP_WAIT0();
    __syncthreads();

    float acc[2][8][4];
#pragma unroll
    for (int a = 0; a < 2; a++)
#pragma unroll
        for (int b = 0; b < 8; b++)
#pragma unroll
            for (int c = 0; c < 4; c++) acc[a][b][c] = 0.f;

    const int a_row = lane & 15, a_kh = lane >> 4;
    const int b_row = (lane & 7) + ((lane >> 4) & 1) * 8;
    const int b_kh = (lane >> 3) & 1;

#pragma unroll
    for (int ks = 0; ks < 4; ks++) {
        unsigned af[2][4], bf[8][2];
#pragma unroll
        for (int mi = 0; mi < 2; mi++) {
            int row = wm + mi * 16 + a_row;
            ldsm_x4(af[mi][0], af[mi][1], af[mi][2], af[mi][3],
                    Ab + (uint32_t)(row * 128 + (((ks * 2 + a_kh) ^ l7) << 4)));
        }
#pragma unroll
        for (int njp = 0; njp < 4; njp++) {
            int row = wn + njp * 16 + b_row;
            ldsm_x4(bf[2 * njp][0], bf[2 * njp][1], bf[2 * njp + 1][0], bf[2 * njp + 1][1],
                    Bb + (uint32_t)(row * 128 + (((ks * 2 + b_kh) ^ l7) << 4)));
        }
#pragma unroll
        for (int mi = 0; mi < 2; mi++)
#pragma unroll
            for (int nj = 0; nj < 8; nj++) MMA_F16(acc[mi][nj], af[mi], bf[nj]);
    }

    float* outp = (wn == 0) ? h : ud;
#pragma unroll
    for (int mi = 0; mi < 2; mi++) {
#pragma unroll
        for (int nj = 0; nj < 8; nj++) {
            int col = n * 64 + nj * 8 + (kc << 1);
            size_t r0 = (size_t)(t0 + wm + mi * 16 + rr);
            *(float2*)(outp + r0 * DD + col) =
                make_float2(silu_f(acc[mi][nj][0]), silu_f(acc[mi][nj][1]));
            *(float2*)(outp + (r0 + 8) * DD + col) =
                make_float2(silu_f(acc[mi][nj][2]), silu_f(acc[mi][nj][3]));
        }
    }
}

// ======== bd192: r = silu(concat @ wpost^T), virtual concat, fp16 out ========
#define BD192_SMEM (3 * 16384 + 3 * 8192)
__global__ void __launch_bounds__(256)
bd192_f16_kernel(const __half* __restrict__ hn, const __half* __restrict__ eh,
                 const __half* __restrict__ Wh, __half* __restrict__ rh) {
    extern __shared__ __align__(16) char smc[];
    const uint32_t Ab = smem_u32(smc);
    const uint32_t Bb = Ab + 3 * 16384;
    const int t0 = blockIdx.x * 128;
    const int n = blockIdx.y;
    const int tid = threadIdx.x;
    const int lane = tid & 31;
    const int warp = tid >> 5;
    const int wm = (warp >> 1) * 32;
    const int wn = (warp & 1) * 32;
    const int rr = lane >> 2, kc = lane & 3, l7 = lane & 7;

#pragma unroll
    for (int c = 0; c < 3; c++) {
        const int pc = 3 * n + c;
        const int part = pc >> 4;
        const int colo = (pc & 15) << 6;
#pragma unroll
        for (int i = 0; i < 4; i++) {
            int cch = tid + i * 256;
            int m = cch >> 3, q = cch & 7;
            int trow = t0 + m;
            uint32_t dst = Ab + c * 16384 + sw_off(m, q);
            if (part == 0) {
                cp16(dst, hn + (size_t)trow * DD + colo + q * 8, 16);
            } else if (part == 1) {
                cp16(dst, eh + (size_t)trow * DD + colo + q * 8, 16);
            } else {
                const __half* src = eh + (size_t)(trow - 1) * DD + colo + q * 8;
                cp16(dst, (trow == 0) ? (const __half*)eh : src, (trow == 0) ? 0 : 16);
            }
        }
#pragma unroll
        for (int i = 0; i < 2; i++) {
            int cch = tid + i * 256;
            int o = cch >> 3, q = cch & 7;
            cp16(Bb + c * 8192 + sw_off(o, q), Wh + (size_t)(n * 64 + o) * 192 + c * 64 + q * 8, 16);
        }
    }
    CP_COMMIT();
    CP_WAIT0();
    __syncthreads();

    float acc[2][4][4];
#pragma unroll
    for (int a = 0; a < 2; a++)
#pragma unroll
        for (int b = 0; b < 4; b++)
#pragma unroll
            for (int c = 0; c < 4; c++) acc[a][b][c] = 0.f;

    const int a_row = lane & 15, a_kh = lane >> 4;
    const int b_row = (lane & 7) + ((lane >> 4) & 1) * 8;
    const int b_kh = (lane >> 3) & 1;

#pragma unroll
    for (int ks = 0; ks < 12; ks++) {
        const int c = ks >> 2, ksl = ks & 3;
        unsigned af[2][4], bf[4][2];
#pragma unroll
        for (int mi = 0; mi < 2; mi++) {
            int row = wm + mi * 16 + a_row;
            ldsm_x4(af[mi][0], af[mi][1], af[mi][2], af[mi][3],
                    Ab + c * 16384 + (uint32_t)(row * 128 + (((ksl * 2 + a_kh) ^ l7) << 4)));
        }
#pragma unroll
        for (int njp = 0; njp < 2; njp++) {
            int row = wn + njp * 16 + b_row;
            ldsm_x4(bf[2 * njp][0], bf[2 * njp][1], bf[2 * njp + 1][0], bf[2 * njp + 1][1],
                    Bb + c * 8192 + (uint32_t)(row * 128 + (((ksl * 2 + b_kh) ^ l7) << 4)));
        }
#pragma unroll
        for (int mi = 0; mi < 2; mi++)
#pragma unroll
            for (int nj = 0; nj < 4; nj++) MMA_F16(acc[mi][nj], af[mi], bf[nj]);
    }

#pragma unroll
    for (int mi = 0; mi < 2; mi++) {
#pragma unroll
        for (int nj = 0; nj < 4; nj++) {
            int col = n * 64 + wn + nj * 8 + (kc << 1);
            size_t r0 = (size_t)(t0 + wm + mi * 16 + rr);
            *(__half2*)(rh + r0 * HH + col) =
                __floats2half2_rn(silu_f(acc[mi][nj][0]), silu_f(acc[mi][nj][1]));
            *(__half2*)(rh + (r0 + 8) * HH + col) =
                __floats2half2_rn(silu_f(acc[mi][nj][2]), silu_f(acc[mi][nj][3]));
        }
    }
}

// ======== update: x += rh@wlocal^T + tmp@lowA^T ========
__global__ void __launch_bounds__(256)
update_f16_kernel(float* __restrict__ x, const __half* __restrict__ rh,
                  const __half* __restrict__ tmph, const __half* __restrict__ wloc,
                  const __half* __restrict__ lowA) {
    __shared__ __half Ash[2][128 * 64];
    __shared__ __half Bsh[2][64 * 64];
    const int t0 = blockIdx.x * 128;
    const int n = blockIdx.y;
    const int tid = threadIdx.x;
    const int lane = tid & 31;
    const int warp = tid >> 5;
    const uint32_t Ab0 = smem_u32(Ash[0]), Ab1 = smem_u32(Ash[1]);
    const uint32_t Bb0 = smem_u32(Bsh[0]), Bb1 = smem_u32(Bsh[1]);
    const int wm = (warp >> 1) * 32;
    const int wn = (warp & 1) * 32;
    const int rr = lane >> 2, kc = lane & 3, l7 = lane & 7;

#pragma unroll
    for (int i = 0; i < 4; i++) {
        int cch = tid + i * 256;
        int m = cch >> 3, q = cch & 7;
        cp16(Ab0 + sw_off(m, q), rh + (size_t)(t0 + m) * HH + n * 64 + q * 8, 16);
        cp16(Ab1 + sw_off(m, q), tmph + (size_t)(t0 + m) * RANKK + q * 8, 16);
    }
#pragma unroll
    for (int i = 0; i < 2; i++) {
        int cch = tid + i * 256;
        int o = cch >> 3, q = cch & 7;
        cp16(Bb0 + sw_off(o, q), wloc + (size_t)(n * 64 + o) * 64 + q * 8, 16);
        cp16(Bb1 + sw_off(o, q), lowA + (size_t)(n * 64 + o) * RANKK + q * 8, 16);
    }
    CP_COMMIT();
    CP_WAIT0();
    __syncthreads();

    float acc[2][4][4];
#pragma unroll
    for (int a = 0; a < 2; a++)
#pragma unroll
        for (int b = 0; b < 4; b++)
#pragma unroll
            for (int c = 0; c < 4; c++) acc[a][b][c] = 0.f;

    const int a_row = lane & 15, a_kh = lane >> 4;
    const int b_row = (lane & 7) + ((lane >> 4) & 1) * 8;
    const int b_kh = (lane >> 3) & 1;

#pragma unroll
    for (int ks = 0; ks < 8; ks++) {
        const int ph = ks >> 2, ksl = ks & 3;
        const uint32_t Ab = ph ? Ab1 : Ab0;
        const uint32_t Bb = ph ? Bb1 : Bb0;
        unsigned af[2][4], bf[4][2];
#pragma unroll
        for (int mi = 0; mi < 2; mi++) {
            int row = wm + mi * 16 + a_row;
            ldsm_x4(af[mi][0], af[mi][1], af[mi][2], af[mi][3],
                    Ab + (uint32_t)(row * 128 + (((ksl * 2 + a_kh) ^ l7) << 4)));
        }
#pragma unroll
        for (int njp = 0; njp < 2; njp++) {
            int row = wn + njp * 16 + b_row;
            ldsm_x4(bf[2 * njp][0], bf[2 * njp][1], bf[2 * njp + 1][0], bf[2 * njp + 1][1],
                    Bb + (uint32_t)(row * 128 + (((ksl * 2 + b_kh) ^ l7) << 4)));
        }
#pragma unroll
        for (int mi = 0; mi < 2; mi++)
#pragma unroll
            for (int nj = 0; nj < 4; nj++) MMA_F16(acc[mi][nj], af[mi], bf[nj]);
    }

#pragma unroll
    for (int mi = 0; mi < 2; mi++) {
#pragma unroll
        for (int nj = 0; nj < 4; nj++) {
            int col = n * 64 + wn + nj * 8 + (kc << 1);
            size_t r0 = (size_t)(t0 + wm + mi * 16 + rr);
            float2* p0 = (float2*)(x + r0 * DD + col);
            float2 v0 = *p0;
            v0.x += acc[mi][nj][0]; v0.y += acc[mi][nj][1];
            *p0 = v0;
            float2* p1 = (float2*)(x + (r0 + 8) * DD + col);
            float2 v1 = *p1;
            v1.x += acc[mi][nj][2]; v1.y += acc[mi][nj][3];
            *p1 = v1;
        }
    }
}

// ======== lowrank1: tmp = rh @ lowB^T ========
__global__ void __launch_bounds__(256)
lowrank1_f16_kernel(const __half* __restrict__ rh, const __half* __restrict__ lowB,
                    __half* __restrict__ tmph) {
    __shared__ __half Ash[2][64 * 64];
    __shared__ __half Bsh[2][64 * 64];
    const int t0 = blockIdx.x * 64;
    const int tid = threadIdx.x;
    const int lane = tid & 31;
    const int warp = tid >> 5;
    const int wm = (warp >> 2) * 32;
    const int wn = (warp & 3) * 16;
    const int rr = lane >> 2, kc = lane & 3, l7 = lane & 7;

#define LR_LOAD(s, kb)                                                                   \
    {                                                                                    \
        _Pragma("unroll") for (int i = 0; i < 2; i++) {                                  \
            int cch = tid + i * 256;                                                     \
            int m = cch >> 3, q = cch & 7;                                               \
            cp16(smem_u32(Ash[s]) + sw_off(m, q),                                        \
                 rh + (size_t)(t0 + m) * HH + (kb) * 64 + q * 8, 16);                    \
            cp16(smem_u32(Bsh[s]) + sw_off(m, q),                                        \
                 lowB + (size_t)m * HH + (kb) * 64 + q * 8, 16);                         \
        }                                                                                \
        CP_COMMIT();                                                                     \
    }

    float acc[2][2][4];
#pragma unroll
    for (int a = 0; a < 2; a++)
#pragma unroll
        for (int b = 0; b < 2; b++)
#pragma unroll
            for (int c = 0; c < 4; c++) acc[a][b][c] = 0.f;

    const int a_row = lane & 15, a_kh = lane >> 4;
    const int b_row = (lane & 7) + ((lane >> 4) & 1) * 8;
    const int b_kh = (lane >> 3) & 1;

    LR_LOAD(0, 0);
    for (int kb = 0; kb < 16; kb++) {
        const int s = kb & 1;
        if (kb + 1 < 16) {
            LR_LOAD(s ^ 1, kb + 1);
            asm volatile("cp.async.wait_group 1;" ::: "memory");
        } else {
            CP_WAIT0();
        }
        __syncthreads();
        const uint32_t Ab = smem_u32(Ash[s]);
        const uint32_t Bb = smem_u32(Bsh[s]);
#pragma unroll
        for (int ks = 0; ks < 4; ks++) {
            unsigned af[2][4], bf[2][2];
#pragma unroll
            for (int mi = 0; mi < 2; mi++) {
                int row = wm + mi * 16 + a_row;
                ldsm_x4(af[mi][0], af[mi][1], af[mi][2], af[mi][3],
                        Ab + (uint32_t)(row * 128 + (((ks * 2 + a_kh) ^ l7) << 4)));
            }
            {
                int row = wn + b_row;
                ldsm_x4(bf[0][0], bf[0][1], bf[1][0], bf[1][1],
                        Bb + (uint32_t)(row * 128 + (((ks * 2 + b_kh) ^ l7) << 4)));
            }
#pragma unroll
            for (int mi = 0; mi < 2; mi++)
#pragma unroll
                for (int nj = 0; nj < 2; nj++) MMA_F16(acc[mi][nj], af[mi], bf[nj]);
        }
        __syncthreads();
    }

#pragma unroll
    for (int mi = 0; mi < 2; mi++) {
#pragma unroll
        for (int nj = 0; nj < 2; nj++) {
            int col = wn + nj * 8 + (kc << 1);
            size_t r0 = (size_t)(t0 + wm + mi * 16 + rr);
            *(__half2*)(tmph + r0 * RANKK + col) =
                __floats2half2_rn(acc[mi][nj][0], acc[mi][nj][1]);
            *(__half2*)(tmph + (r0 + 8) * RANKK + col) =
                __floats2half2_rn(acc[mi][nj][2], acc[mi][nj][3]);
        }
    }
}

// ============ causal scan, 3-phase chunked (fp32, exact) ============
__global__ void scanA_kernel(float* __restrict__ buf, const float* __restrict__ logA,
                             const float* __restrict__ logdt, float* __restrict__ seg) {
    int d = blockIdx.x * 32 + threadIdx.x;
    int s = blockIdx.y * 8 + threadIdx.y;
    float a = expf(-expf(logA[d]) * expf(logdt[d]));
    float y = 0.f;
    int t0 = s * SEGLEN;
#pragma unroll 8
    for (int tt = 0; tt < SEGLEN; tt++) {
        int i = (t0 + tt) * DD + d;
        y = a * y + buf[i];
        buf[i] = y;
    }
    seg[s * DD + d] = y;
}

__global__ void scanB_kernel(float* __restrict__ seg, const float* __restrict__ logA,
                             const float* __restrict__ logdt) {
    int d = blockIdx.x * 16 + threadIdx.x;
    int j = threadIdx.y;
    float a = expf(-expf(logA[d]) * expf(logdt[d]));
    float a32 = a;
#pragma unroll
    for (int q = 0; q < 5; q++) a32 *= a32;
    __shared__ float s[NSEG][17];
    float cur = seg[j * DD + d];
    s[j][threadIdx.x] = cur;
    float m = a32;
    for (int st = 1; st < NSEG; st <<= 1) {
        __syncthreads();
        float prev = (j >= st) ? s[j - st][threadIdx.x] : 0.f;
        __syncthreads();
        cur += m * prev;
        s[j][threadIdx.x] = cur;
        m = m * m;
    }
    seg[j * DD + d] = cur;
}

__global__ void scanC_kernel(float* __restrict__ buf, const float* __restrict__ logA,
                             const float* __restrict__ logdt, const float* __restrict__ seg) {
    int d = blockIdx.x * 32 + threadIdx.x;
    int s = blockIdx.y * 8 + threadIdx.y;
    if (s == 0) return;
    float a = expf(-expf(logA[d]) * expf(logdt[d]));
    float carry = seg[(s - 1) * DD + d];
    float f = a;
    int t0 = s * SEGLEN;
#pragma unroll 8
    for (int tt = 0; tt < SEGLEN; tt++) {
        int i = (t0 + tt) * DD + d;
        buf[i] += f * carry;
        f *= a;
    }
}

// ---------------- combine: hn = rmsnorm(hseq + gain*ud) -> fp16 ----------------
__global__ void combine_kernel(const float* __restrict__ h, const float* __restrict__ udep,
                               const float* __restrict__ logAd, const float* __restrict__ logdtd,
                               const int* __restrict__ pK, __half* __restrict__ hn) {
    int t = blockIdx.x;
    int tid = threadIdx.x;
    int K = *pK;
    float hv[4];
    float ss = 0.f;
#pragma unroll
    for (int r = 0; r < 4; r++) {
        int d = tid + r * 256;
        float g;
        if (d < NMEM) {
            g = (float)K;
        } else {
            float aD = expf(-expf(logAd[d - NMEM]) * expf(logdtd[d - NMEM]));
            float om = 1.f - aD;
            float safe = fmaxf(om, 1e-8f);
            float p = 1.f;
            for (int k = 0; k < K; k++) p *= aD;
            g = (fabsf(om) < 1e-6f) ? (float)K : (1.f - p) / safe;
        }
        float hx = h[t * DD + d] + g * udep[t * DD + d];
        hv[r] = hx;
        ss += hx * hx;
    }
    __shared__ float red[256];
    red[tid] = ss;
    __syncthreads();
    for (int s = 128; s > 0; s >>= 1) {
        if (tid < s) red[tid] += red[tid + s];
        __syncthreads();
    }
    float sc = rsqrtf(red[0] / (float)DD + RMS_EPS);
#pragma unroll
    for (int r = 0; r < 4; r++) {
        int d = tid + r * 256;
        hn[t * DD + d] = __float2half_rn(hv[r] * sc);
    }
}

// ======= LM head GEMM: persistent CTAs, fp16 m16n8k16, ldmatrix+SW128, 4-stage ========
#define A_ST 16384
#define B_ST 32768
#define NSTG 4
#define LM_SMEM (NSTG * (A_ST + B_ST))
#define GPERS 152
#define NTILES (16 * 197)  // (TT/128) x ceil(VV/256)

__global__ void __launch_bounds__(256, 1)
lmhead_gemm(const __half* __restrict__ A, const __half* __restrict__ B, float* __restrict__ C) {
    extern __shared__ __align__(16) char smc[];
    const uint32_t smb = smem_u32(smc);
    const int tid = threadIdx.x;
    const int lane = tid & 31;
    const int warp = tid >> 5;
    const int bid = blockIdx.x;
    const int wm = (warp >> 2) * 64;
    const int wn = (warp & 3) * 64;
    const int rr = lane >> 2;
    const int kc = lane & 3;
    const int l7 = lane & 7;

    float acc[4][8][4];
#pragma unroll
    for (int i = 0; i < 4; i++)
#pragma unroll
        for (int j = 0; j < 8; j++)
#pragma unroll
            for (int k = 0; k < 4; k++) acc[i][j][k] = 0.f;

    // chunk j -> tile tt = bid + (j>>4)*GPERS, kb = j&15, stage = j&3
#define LOAD_CHUNK(j_)                                                                 \
    {                                                                                  \
        int tt_ = bid + ((j_) >> 4) * GPERS;                                           \
        if (tt_ < NTILES) {                                                            \
            int kb_ = (j_) & 15;                                                       \
            int s_ = (j_) & 3;                                                         \
            int M0_ = (tt_ & 15) * 128;                                                \
            int N0_ = (tt_ >> 4) * 256;                                                \
            int nVal_ = (VV - N0_ < 256) ? (VV - N0_) : 256;                           \
            _Pragma("unroll") for (int i = 0; i < 4; i++) {                            \
                int cch = tid + i * 256;                                               \
                int m = cch >> 3, q = cch & 7;                                         \
                uint32_t dst = smb + s_ * A_ST + (uint32_t)(m * 128 + ((q ^ (m & 7)) << 4)); \
                cp16(dst, A + (size_t)(M0_ + m) * DD + kb_ * 64 + q * 8, 16);          \
            }                                                                          \
            _Pragma("unroll") for (int i = 0; i < 8; i++) {                            \
                int cch = tid + i * 256;                                               \
                int n = cch >> 3, q = cch & 7;                                         \
                uint32_t dst = smb + NSTG * A_ST + s_ * B_ST +                         \
                               (uint32_t)(n * 128 + ((q ^ (n & 7)) << 4));             \
                int ok = (n < nVal_);                                                  \
                cp16(dst, B + (size_t)(N0_ + (ok ? n : 0)) * DD + kb_ * 64 + q * 8,    \
                     ok ? 16 : 0);                                                     \
            }                                                                          \
        }                                                                              \
        CP_COMMIT();                                                                   \
    }

    const int myTiles = (NTILES - 1 - bid) / GPERS + 1;
    const int J = myTiles * 16;

    LOAD_CHUNK(0);
    LOAD_CHUNK(1);
    LOAD_CHUNK(2);

    const int a_row = (lane & 15);
    const int a_kh = lane >> 4;
    const int b_row = (lane & 7) + ((lane >> 4) & 1) * 8;
    const int b_kh = (lane >> 3) & 1;

    for (int j = 0; j < J; j++) {
        asm volatile("cp.async.wait_group 2;" ::: "memory");
        __syncthreads();
        LOAD_CHUNK(j + 3);

        const int s = j & 3;
        const uint32_t Ab = smb + s * A_ST;
        const uint32_t Bb = smb + NSTG * A_ST + s * B_ST;

#pragma unroll
        for (int ks = 0; ks < 4; ks++) {
            unsigned af[4][4], bf[8][2];
#pragma unroll
            for (int mi = 0; mi < 4; mi++) {
                int row = wm + mi * 16 + a_row;
                int chunk = (ks * 2 + a_kh) ^ l7;
                ldsm_x4(af[mi][0], af[mi][1], af[mi][2], af[mi][3],
                        Ab + (uint32_t)(row * 128 + (chunk << 4)));
            }
#pragma unroll
            for (int njp = 0; njp < 4; njp++) {
                int row = wn + njp * 16 + b_row;
                int chunk = (ks * 2 + b_kh) ^ l7;
                ldsm_x4(bf[2 * njp][0], bf[2 * njp][1], bf[2 * njp + 1][0], bf[2 * njp + 1][1],
                        Bb + (uint32_t)(row * 128 + (chunk << 4)));
            }
#pragma unroll
            for (int mi = 0; mi < 4; mi++)
#pragma unroll
                for (int nj = 0; nj < 8; nj++) MMA_F16(acc[mi][nj], af[mi], bf[nj]);
        }

        if ((j & 15) == 15) {
            // epilogue for tile
            int tt = bid + (j >> 4) * GPERS;
            int M0 = (tt & 15) * 128;
            int N0 = (tt >> 4) * 256;
#pragma unroll
            for (int mi = 0; mi < 4; mi++) {
#pragma unroll
                for (int nj = 0; nj < 8; nj++) {
                    int c0 = N0 + wn + nj * 8 + (kc << 1);
                    if (c0 < VV) {
                        size_t r0 = (size_t)(M0 + wm + mi * 16 + rr);
                        __stcs((float2*)(C + r0 * VV + c0),
                               make_float2(acc[mi][nj][0] * BSCALE_INV,
                                           acc[mi][nj][1] * BSCALE_INV));
                        __stcs((float2*)(C + (r0 + 8) * VV + c0),
                               make_float2(acc[mi][nj][2] * BSCALE_INV,
                                           acc[mi][nj][3] * BSCALE_INV));
                    }
#pragma unroll
                    for (int k = 0; k < 4; k++) acc[mi][nj][k] = 0.f;
                }
            }
        }
    }
}

// ---------------- launcher ----------------
extern "C" void kernel_launch(void* const* d_in, const int* in_sizes, int n_in,
                              void* d_out, int out_size) {
    const int* idx = (const int*)d_in[0];
    const int* pK = (const int*)d_in[1];
    const float* wte = (const float*)d_in[2];
    const float* wpe = (const float*)d_in[3];
    const float* bseq_w = (const float*)d_in[4];
    const float* logA_seq = (const float*)d_in[5];
    const float* logdt_seq = (const float*)d_in[6];
    const float* bdepth_w = (const float*)d_in[7];
    const float* logA_depth = (const float*)d_in[8];
    const float* logdt_depth = (const float*)d_in[9];
    const float* wpost_w = (const float*)d_in[10];
    const float* wlocal_w = (const float*)d_in[11];
    const float* lowA = (const float*)d_in[12];
    const float* lowB = (const float*)d_in[13];
    const float* lm_head_w = (const float*)d_in[14];
    float* out = (float*)d_out;

    float *x, *h, *ud, *seg;
    __half *eh, *hn, *rh, *tmph, *xh, *Bh;
    __half *bseqh, *bdeph, *wposth, *wloch, *lowAh, *lowBh;
    cudaGetSymbolAddress((void**)&x, g_x);
    cudaGetSymbolAddress((void**)&h, g_h);
    cudaGetSymbolAddress((void**)&ud, g_ud);
    cudaGetSymbolAddress((void**)&seg, g_seg);
    cudaGetSymbolAddress((void**)&eh, g_eh);
    cudaGetSymbolAddress((void**)&hn, g_hn);
    cudaGetSymbolAddress((void**)&rh, g_rh);
    cudaGetSymbolAddress((void**)&tmph, g_tmph);
    cudaGetSymbolAddress((void**)&xh, g_xh);
    cudaGetSymbolAddress((void**)&Bh, g_Bh);
    cudaGetSymbolAddress((void**)&bseqh, g_bseqh);
    cudaGetSymbolAddress((void**)&bdeph, g_bdeph);
    cudaGetSymbolAddress((void**)&wposth, g_wposth);
    cudaGetSymbolAddress((void**)&wloch, g_wloch);
    cudaGetSymbolAddress((void**)&lowAh, g_lowAh);
    cudaGetSymbolAddress((void**)&lowBh, g_lowBh);

    cudaFuncSetAttribute(lmhead_gemm, cudaFuncAttributeMaxDynamicSharedMemorySize, LM_SMEM);
    cudaFuncSetAttribute(bd192_f16_kernel, cudaFuncAttributeMaxDynamicSharedMemorySize, BD192_SMEM);

    // weight conversions
    f16_convert_kernel<<<(VV * DD / 8) / 256, 256>>>(lm_head_w, Bh);
    conv5_f16_kernel<<<dim3(LYR * NBLK * 64 * 64 / 8 / 256, 5), 256>>>(
        bseq_w, bseqh, bdepth_w, bdeph, wlocal_w, wloch, lowA, lowAh, lowB, lowBh);
    conv_f16_kernel<<<LYR * NBLK * 64 * 192 / 8 / 256, 256>>>(wpost_w, wposth);

    embed_kernel<<<TT, 256>>>(idx, wte, wpe, x);

    for (int l = 0; l < LYR; l++) {
        const __half* bseq_l = bseqh + l * NBLK * 64 * 64;
        const __half* bdep_l = bdeph + l * NBLK * 64 * 64;
        const __half* wpost_l = wposth + l * NBLK * 64 * 192;
        const __half* wlocal_l = wloch + l * NBLK * 64 * 64;
        const __half* lowA_l = lowAh + l * DD * RANKK;
        const __half* lowB_l = lowBh + l * RANKK * HH;
        const float* lAs = logA_seq + l * HH;
        const float* lDs = logdt_seq + l * HH;
        const float* lAd = logA_depth + l * (HH - NMEM);
        const float* lDd = logdt_depth + l * (HH - NMEM);

        rmsnorm_f16_kernel<<<TT, 256>>>(x, eh);
        bd64_f16_kernel<<<dim3(TT / 128, NBLK), 256>>>(eh, bseq_l, bdep_l, h, ud);
        scanA_kernel<<<dim3(32, 8), dim3(32, 8)>>>(h, lAs, lDs, seg);
        scanB_kernel<<<DD / 16, dim3(16, NSEG)>>>(seg, lAs, lDs);
        scanC_kernel<<<dim3(32, 8), dim3(32, 8)>>>(h, lAs, lDs, seg);
        combine_kernel<<<TT, 256>>>(h, ud, lAd, lDd, pK, hn);
        bd192_f16_kernel<<<dim3(TT / 128, NBLK), 256, BD192_SMEM>>>(hn, eh, wpost_l, rh);
        lowrank1_f16_kernel<<<TT / 64, 256>>>(rh, lowB_l, tmph);
        update_f16_kernel<<<dim3(TT / 128, NBLK), 256>>>(x, rh, tmph, wlocal_l, lowA_l);
    }

    rmsnorm_f16_kernel<<<TT, 256>>>(x, xh);
    lmhead_gemm<<<GPERS, 256, LM_SMEM>>>(xh, Bh, out);
}

// round 16
// speedup vs baseline: 1.5761x; 1.0018x over previous
#include <cuda_runtime.h>
#include <cuda_bf16.h>
#include <cuda_fp16.h>
#include <math.h>
#include <stdint.h>

#define TT 2048
#define DD 1024
#define HH 1024
#define NBLK 16
#define LYR 4
#define RANKK 64
#define NMEM 64
#define VV 50304
#define RMS_EPS 1.1920929e-7f
#define SEGLEN 32
#define NSEG 64
#define BSCALE 1024.0f
#define BSCALE_INV 0.0009765625f

// ---------------- scratch ----------------
__device__ float g_x[TT * DD];
__device__ float g_h[TT * DD];
__device__ float g_ud[TT * DD];
__device__ float g_seg[NSEG * DD];
__device__ __half g_eh[TT * DD];
__device__ __half g_hn[TT * DD];
__device__ __half g_rh[TT * HH];
__device__ __half g_tmph[TT * RANKK];
__device__ __half g_xh[TT * DD];
__device__ __half g_Bh[(size_t)VV * DD];
__device__ __half g_bseqh[LYR * NBLK * 64 * 64];
__device__ __half g_bdeph[LYR * NBLK * 64 * 64];
__device__ __half g_wposth[LYR * NBLK * 64 * 192];
__device__ __half g_wloch[LYR * NBLK * 64 * 64];
__device__ __half g_lowAh[LYR * DD * RANKK];
__device__ __half g_lowBh[LYR * RANKK * HH];

// ---------------- helpers ----------------
__device__ __forceinline__ float silu_f(float x) { return x / (1.0f + expf(-x)); }

__device__ __forceinline__ uint32_t smem_u32(const void* p) {
    uint32_t a;
    asm("{ .reg .u64 t; cvta.to.shared.u64 t, %1; cvt.u32.u64 %0, t; }" : "=r"(a) : "l"(p));
    return a;
}
__device__ __forceinline__ void cp16(uint32_t dst, const void* src, int sz) {
    asm volatile("cp.async.cg.shared.global [%0], [%1], 16, %2;"
                 :: "r"(dst), "l"(src), "r"(sz) : "memory");
}
#define CP_COMMIT() asm volatile("cp.async.commit_group;" ::: "memory")
#define CP_WAIT0() asm volatile("cp.async.wait_group 0;" ::: "memory")

__device__ __forceinline__ void ldsm_x4(unsigned& r0, unsigned& r1, unsigned& r2, unsigned& r3,
                                        uint32_t addr) {
    asm volatile("ldmatrix.sync.aligned.m8n8.x4.shared.b16 {%0,%1,%2,%3}, [%4];"
                 : "=r"(r0), "=r"(r1), "=r"(r2), "=r"(r3) : "r"(addr));
}

#define MMA_F16(c, a, b)                                                               \
    asm volatile(                                                                      \
        "mma.sync.aligned.m16n8k16.row.col.f32.f16.f16.f32 "                           \
        "{%0,%1,%2,%3},{%4,%5,%6,%7},{%8,%9},{%0,%1,%2,%3};\n"                         \
        : "+f"(c[0]), "+f"(c[1]), "+f"(c[2]), "+f"(c[3])                               \
        : "r"(a[0]), "r"(a[1]), "r"(a[2]), "r"(a[3]), "r"(b[0]), "r"(b[1]))

__device__ __forceinline__ uint32_t sw_off(int row, int q) {
    return (uint32_t)(row * 128 + ((q ^ (row & 7)) << 4));
}

// ---------------- embedding ----------------
__global__ void embed_kernel(const int* __restrict__ idx, const float* __restrict__ wte,
                             const float* __restrict__ wpe, float* __restrict__ x) {
    int t = blockIdx.x;
    int row = idx[t];
    const float4* wrow = (const float4*)(wte + (long)row * DD);
    const float4* prow = (const float4*)(wpe + (long)t * DD);
    float4* xo = (float4*)(x + t * DD);
    for (int d = threadIdx.x; d < DD / 4; d += blockDim.x) {
        float4 a = wrow[d], b = prow[d];
        xo[d] = make_float4(a.x + b.x, a.y + b.y, a.z + b.z, a.w + b.w);
    }
}

// ---------------- rmsnorm -> fp16 ----------------
__global__ void rmsnorm_f16_kernel(const float* __restrict__ in, __half* __restrict__ out) {
    int t = blockIdx.x;
    int tid = threadIdx.x;
    float4 v = ((const float4*)(in + t * DD))[tid];
    float ss = v.x * v.x + v.y * v.y + v.z * v.z + v.w * v.w;
    __shared__ float red[256];
    red[tid] = ss;
    __syncthreads();
    for (int s = 128; s > 0; s >>= 1) {
        if (tid < s) red[tid] += red[tid + s];
        __syncthreads();
    }
    float sc = rsqrtf(red[0] / (float)DD + RMS_EPS);
    __half2 h0 = __floats2half2_rn(v.x * sc, v.y * sc);
    __half2 h1 = __floats2half2_rn(v.z * sc, v.w * sc);
    ((__half2*)(out + t * DD))[tid * 2] = h0;
    ((__half2*)(out + t * DD))[tid * 2 + 1] = h1;
}

// lm_head weights: *1024, fp16
__global__ void f16_convert_kernel(const float* __restrict__ in, __half* __restrict__ out) {
    size_t i = (size_t)blockIdx.x * blockDim.x + threadIdx.x;
    const float4* in4 = (const float4*)in + i * 2;
    float4 a = in4[0], b = in4[1];
    __half h[8];
    h[0] = __float2half_rn(a.x * BSCALE); h[1] = __float2half_rn(a.y * BSCALE);
    h[2] = __float2half_rn(a.z * BSCALE); h[3] = __float2half_rn(a.w * BSCALE);
    h[4] = __float2half_rn(b.x * BSCALE); h[5] = __float2half_rn(b.y * BSCALE);
    h[6] = __float2half_rn(b.z * BSCALE); h[7] = __float2half_rn(b.w * BSCALE);
    ((uint4*)(out + i * 8))[0] = *(uint4*)&h[0];
}

// convert 5 equal-size fp32 arrays -> fp16 (blockIdx.y selects array)
__global__ void conv5_f16_kernel(const float* __restrict__ p0, __half* __restrict__ q0,
                                 const float* __restrict__ p1, __half* __restrict__ q1,
                                 const float* __restrict__ p2, __half* __restrict__ q2,
                                 const float* __restrict__ p3, __half* __restrict__ q3,
                                 const float* __restrict__ p4, __half* __restrict__ q4) {
    const float* in;
    __half* out;
    switch (blockIdx.y) {
        case 0: in = p0; out = q0; break;
        case 1: in = p1; out = q1; break;
        case 2: in = p2; out = q2; break;
        case 3: in = p3; out = q3; break;
        default: in = p4; out = q4; break;
    }
    size_t i = (size_t)blockIdx.x * blockDim.x + threadIdx.x;
    const float4* in4 = (const float4*)in + i * 2;
    float4 a = in4[0], b = in4[1];
    __half h[8];
    h[0] = __float2half_rn(a.x); h[1] = __float2half_rn(a.y);
    h[2] = __float2half_rn(a.z); h[3] = __float2half_rn(a.w);
    h[4] = __float2half_rn(b.x); h[5] = __float2half_rn(b.y);
    h[6] = __float2half_rn(b.z); h[7] = __float2half_rn(b.w);
    ((uint4*)(out + i * 8))[0] = *(uint4*)&h[0];
}

__global__ void conv_f16_kernel(const float* __restrict__ in, __half* __restrict__ out) {
    size_t i = (size_t)blockIdx.x * blockDim.x + threadIdx.x;
    const float4* in4 = (const float4*)in + i * 2;
    float4 a = in4[0], b = in4[1];
    __half h[8];
    h[0] = __float2half_rn(a.x); h[1] = __float2half_rn(a.y);
    h[2] = __float2half_rn(a.z); h[3] = __float2half_rn(a.w);
    h[4] = __float2half_rn(b.x); h[5] = __float2half_rn(b.y);
    h[6] = __float2half_rn(b.z); h[7] = __float2half_rn(b.w);
    ((uint4*)(out + i * 8))[0] = *(uint4*)&h[0];
}

// ======== bd64 dual: h=silu(e@W1^T), ud=silu(e@W2^T). M=128, N=128(W1|W2), K=64 =========
__global__ void __launch_bounds__(256)
bd64_f16_kernel(const __half* __restrict__ eh, const __half* __restrict__ W1h,
                const __half* __restrict__ W2h, float* __restrict__ h, float* __restrict__ ud) {
    __shared__ __half Ash[128 * 64];
    __shared__ __half Bsh[128 * 64];
    const int t0 = blockIdx.x * 128;
    const int n = blockIdx.y;
    const int tid = threadIdx.x;
    const int lane = tid & 31;
    const int warp = tid >> 5;
    const uint32_t Ab = smem_u32(Ash), Bb = smem_u32(Bsh);
    const int wm = (warp >> 1) * 32;
    const int wn = (warp & 1) * 64;
    const int rr = lane >> 2, kc = lane & 3, l7 = lane & 7;

#pragma unroll
    for (int i = 0; i < 4; i++) {
        int cch = tid + i * 256;
        int m = cch >> 3, q = cch & 7;
        cp16(Ab + sw_off(m, q), eh + (size_t)(t0 + m) * DD + n * 64 + q * 8, 16);
        const __half* wsrc = (m < 64) ? (W1h + (n * 64 + m) * 64 + q * 8)
                                      : (W2h + (n * 64 + m - 64) * 64 + q * 8);
        cp16(Bb + sw_off(m, q), wsrc, 16);
    }
    CP_COMMIT();
    CP_WAIT0();
    __syncthreads();

    float acc[2][8][4];
#pragma unroll
    for (int a = 0; a < 2; a++)
#pragma unroll
        for (int b = 0; b < 8; b++)
#pragma unroll
            for (int c = 0; c < 4; c++) acc[a][b][c] = 0.f;

    const int a_row = lane & 15, a_kh = lane >> 4;
    const int b_row = (lane & 7) + ((lane >> 4) & 1) * 8;
    const int b_kh = (lane >> 3) & 1;

#pragma unroll
    for (int ks = 0; ks < 4; ks++) {
        unsigned af[2][4], bf[8][2];
#pragma unroll
        for (int mi = 0; mi < 2; mi++) {
            int row = wm + mi * 16 + a_row;
            ldsm_x4(af[mi][0], af[mi][1], af[mi][2], af[mi][3],
                    Ab + (uint32_t)(row * 128 + (((ks * 2 + a_kh) ^ l7) << 4)));
        }
#pragma unroll
        for (int njp = 0; njp < 4; njp++) {
            int row = wn + njp * 16 + b_row;
            ldsm_x4(bf[2 * njp][0], bf[2 * njp][1], bf[2 * njp + 1][0], bf[2 * njp + 1][1],
                    Bb + (uint32_t)(row * 128 + (((ks * 2 + b_kh) ^ l7) << 4)));
        }
#pragma unroll
        for (int mi = 0; mi < 2; mi++)
#pragma unroll
            for (int nj = 0; nj < 8; nj++) MMA_F16(acc[mi][nj], af[mi], bf[nj]);
    }

    float* outp = (wn == 0) ? h : ud;
#pragma unroll
    for (int mi = 0; mi < 2; mi++) {
#pragma unroll
        for (int nj = 0; nj < 8; nj++) {
            int col = n * 64 + nj * 8 + (kc << 1);
            size_t r0 = (size_t)(t0 + wm + mi * 16 + rr);
            *(float2*)(outp + r0 * DD + col) =
                make_float2(silu_f(acc[mi][nj][0]), silu_f(acc[mi][nj][1]));
            *(float2*)(outp + (r0 + 8) * DD + col) =
                make_float2(silu_f(acc[mi][nj][2]), silu_f(acc[mi][nj][3]));
        }
    }
}

// ======== bd192: r = silu(concat @ wpost^T), virtual concat, fp16 out ========
#define BD192_SMEM (3 * 16384 + 3 * 8192)
__global__ void __launch_bounds__(256)
bd192_f16_kernel(const __half* __restrict__ hn, const __half* __restrict__ eh,
                 const __half* __restrict__ Wh, __half* __restrict__ rh) {
    extern __shared__ __align__(16) char smc[];
    const uint32_t Ab = smem_u32(smc);
    const uint32_t Bb = Ab + 3 * 16384;
    const int t0 = blockIdx.x * 128;
    const int n = blockIdx.y;
    const int tid = threadIdx.x;
    const int lane = tid & 31;
    const int warp = tid >> 5;
    const int wm = (warp >> 1) * 32;
    const int wn = (warp & 1) * 32;
    const int rr = lane >> 2, kc = lane & 3, l7 = lane & 7;

#pragma unroll
    for (int c = 0; c < 3; c++) {
        const int pc = 3 * n + c;
        const int part = pc >> 4;
        const int colo = (pc & 15) << 6;
#pragma unroll
        for (int i = 0; i < 4; i++) {
            int cch = tid + i * 256;
            int m = cch >> 3, q = cch & 7;
            int trow = t0 + m;
            uint32_t dst = Ab + c * 16384 + sw_off(m, q);
            if (part == 0) {
                cp16(dst, hn + (size_t)trow * DD + colo + q * 8, 16);
            } else if (part == 1) {
                cp16(dst, eh + (size_t)trow * DD + colo + q * 8, 16);
            } else {
                const __half* src = eh + (size_t)(trow - 1) * DD + colo + q * 8;
                cp16(dst, (trow == 0) ? (const __half*)eh : src, (trow == 0) ? 0 : 16);
            }
        }
#pragma unroll
        for (int i = 0; i < 2; i++) {
            int cch = tid + i * 256;
            int o = cch >> 3, q = cch & 7;
            cp16(Bb + c * 8192 + sw_off(o, q), Wh + (size_t)(n * 64 + o) * 192 + c * 64 + q * 8, 16);
        }
    }
    CP_COMMIT();
    CP_WAIT0();
    __syncthreads();

    float acc[2][4][4];
#pragma unroll
    for (int a = 0; a < 2; a++)
#pragma unroll
        for (int b = 0; b < 4; b++)
#pragma unroll
            for (int c = 0; c < 4; c++) acc[a][b][c] = 0.f;

    const int a_row = lane & 15, a_kh = lane >> 4;
    const int b_row = (lane & 7) + ((lane >> 4) & 1) * 8;
    const int b_kh = (lane >> 3) & 1;

#pragma unroll
    for (int ks = 0; ks < 12; ks++) {
        const int c = ks >> 2, ksl = ks & 3;
        unsigned af[2][4], bf[4][2];
#pragma unroll
        for (int mi = 0; mi < 2; mi++) {
            int row = wm + mi * 16 + a_row;
            ldsm_x4(af[mi][0], af[mi][1], af[mi][2], af[mi][3],
                    Ab + c * 16384 + (uint32_t)(row * 128 + (((ksl * 2 + a_kh) ^ l7) << 4)));
        }
#pragma unroll
        for (int njp = 0; njp < 2; njp++) {
            int row = wn + njp * 16 + b_row;
            ldsm_x4(bf[2 * njp][0], bf[2 * njp][1], bf[2 * njp + 1][0], bf[2 * njp + 1][1],
                    Bb + c * 8192 + (uint32_t)(row * 128 + (((ksl * 2 + b_kh) ^ l7) << 4)));
        }
#pragma unroll
        for (int mi = 0; mi < 2; mi++)
#pragma unroll
            for (int nj = 0; nj < 4; nj++) MMA_F16(acc[mi][nj], af[mi], bf[nj]);
    }

#pragma unroll
    for (int mi = 0; mi < 2; mi++) {
#pragma unroll
        for (int nj = 0; nj < 4; nj++) {
            int col = n * 64 + wn + nj * 8 + (kc << 1);
            size_t r0 = (size_t)(t0 + wm + mi * 16 + rr);
            *(__half2*)(rh + r0 * HH + col) =
                __floats2half2_rn(silu_f(acc[mi][nj][0]), silu_f(acc[mi][nj][1]));
            *(__half2*)(rh + (r0 + 8) * HH + col) =
                __floats2half2_rn(silu_f(acc[mi][nj][2]), silu_f(acc[mi][nj][3]));
        }
    }
}

// ======== update: x += rh@wlocal^T + tmp@lowA^T ========
__global__ void __launch_bounds__(256)
update_f16_kernel(float* __restrict__ x, const __half* __restrict__ rh,
                  const __half* __restrict__ tmph, const __half* __restrict__ wloc,
                  const __half* __restrict__ lowA) {
    __shared__ __half Ash[2][128 * 64];
    __shared__ __half Bsh[2][64 * 64];
    const int t0 = blockIdx.x * 128;
    const int n = blockIdx.y;
    const int tid = threadIdx.x;
    const int lane = tid & 31;
    const int warp = tid >> 5;
    const uint32_t Ab0 = smem_u32(Ash[0]), Ab1 = smem_u32(Ash[1]);
    const uint32_t Bb0 = smem_u32(Bsh[0]), Bb1 = smem_u32(Bsh[1]);
    const int wm = (warp >> 1) * 32;
    const int wn = (warp & 1) * 32;
    const int rr = lane >> 2, kc = lane & 3, l7 = lane & 7;

#pragma unroll
    for (int i = 0; i < 4; i++) {
        int cch = tid + i * 256;
        int m = cch >> 3, q = cch & 7;
        cp16(Ab0 + sw_off(m, q), rh + (size_t)(t0 + m) * HH + n * 64 + q * 8, 16);
        cp16(Ab1 + sw_off(m, q), tmph + (size_t)(t0 + m) * RANKK + q * 8, 16);
    }
#pragma unroll
    for (int i = 0; i < 2; i++) {
        int cch = tid + i * 256;
        int o = cch >> 3, q = cch & 7;
        cp16(Bb0 + sw_off(o, q), wloc + (size_t)(n * 64 + o) * 64 + q * 8, 16);
        cp16(Bb1 + sw_off(o, q), lowA + (size_t)(n * 64 + o) * RANKK + q * 8, 16);
    }
    CP_COMMIT();
    CP_WAIT0();
    __syncthreads();

    float acc[2][4][4];
#pragma unroll
    for (int a = 0; a < 2; a++)
#pragma unroll
        for (int b = 0; b < 4; b++)
#pragma unroll
            for (int c = 0; c < 4; c++) acc[a][b][c] = 0.f;

    const int a_row = lane & 15, a_kh = lane >> 4;
    const int b_row = (lane & 7) + ((lane >> 4) & 1) * 8;
    const int b_kh = (lane >> 3) & 1;

#pragma unroll
    for (int ks = 0; ks < 8; ks++) {
        const int ph = ks >> 2, ksl = ks & 3;
        const uint32_t Ab = ph ? Ab1 : Ab0;
        const uint32_t Bb = ph ? Bb1 : Bb0;
        unsigned af[2][4], bf[4][2];
#pragma unroll
        for (int mi = 0; mi < 2; mi++) {
            int row = wm + mi * 16 + a_row;
            ldsm_x4(af[mi][0], af[mi][1], af[mi][2], af[mi][3],
                    Ab + (uint32_t)(row * 128 + (((ksl * 2 + a_kh) ^ l7) << 4)));
        }
#pragma unroll
        for (int njp = 0; njp < 2; njp++) {
            int row = wn + njp * 16 + b_row;
            ldsm_x4(bf[2 * njp][0], bf[2 * njp][1], bf[2 * njp + 1][0], bf[2 * njp + 1][1],
                    Bb + (uint32_t)(row * 128 + (((ksl * 2 + b_kh) ^ l7) << 4)));
        }
#pragma unroll
        for (int mi = 0; mi < 2; mi++)
#pragma unroll
            for (int nj = 0; nj < 4; nj++) MMA_F16(acc[mi][nj], af[mi], bf[nj]);
    }

#pragma unroll
    for (int mi = 0; mi < 2; mi++) {
#pragma unroll
        for (int nj = 0; nj < 4; nj++) {
            int col = n * 64 + wn + nj * 8 + (kc << 1);
            size_t r0 = (size_t)(t0 + wm + mi * 16 + rr);
            float2* p0 = (float2*)(x + r0 * DD + col);
            float2 v0 = *p0;
            v0.x += acc[mi][nj][0]; v0.y += acc[mi][nj][1];
            *p0 = v0;
            float2* p1 = (float2*)(x + (r0 + 8) * DD + col);
            float2 v1 = *p1;
            v1.x += acc[mi][nj][2]; v1.y += acc[mi][nj][3];
            *p1 = v1;
        }
    }
}

// ======== lowrank1: tmp = rh @ lowB^T ========
__global__ void __launch_bounds__(256)
lowrank1_f16_kernel(const __half* __restrict__ rh, const __half* __restrict__ lowB,
                    __half* __restrict__ tmph) {
    __shared__ __half Ash[2][64 * 64];
    __shared__ __half Bsh[2][64 * 64];
    const int t0 = blockIdx.x * 64;
    const int tid = threadIdx.x;
    const int lane = tid & 31;
    const int warp = tid >> 5;
    const int wm = (warp >> 2) * 32;
    const int wn = (warp & 3) * 16;
    const int rr = lane >> 2, kc = lane & 3, l7 = lane & 7;

#define LR_LOAD(s, kb)                                                                   \
    {                                                                                    \
        _Pragma("unroll") for (int i = 0; i < 2; i++) {                                  \
            int cch = tid + i * 256;                                                     \
            int m = cch >> 3, q = cch & 7;                                               \
            cp16(smem_u32(Ash[s]) + sw_off(m, q),                                        \
                 rh + (size_t)(t0 + m) * HH + (kb) * 64 + q * 8, 16);                    \
            cp16(smem_u32(Bsh[s]) + sw_off(m, q),                                        \
                 lowB + (size_t)m * HH + (kb) * 64 + q * 8, 16);                         \
        }                                                                                \
        CP_COMMIT();                                                                     \
    }

    float acc[2][2][4];
#pragma unroll
    for (int a = 0; a < 2; a++)
#pragma unroll
        for (int b = 0; b < 2; b++)
#pragma unroll
            for (int c = 0; c < 4; c++) acc[a][b][c] = 0.f;

    const int a_row = lane & 15, a_kh = lane >> 4;
    const int b_row = (lane & 7) + ((lane >> 4) & 1) * 8;
    const int b_kh = (lane >> 3) & 1;

    LR_LOAD(0, 0);
    for (int kb = 0; kb < 16; kb++) {
        const int s = kb & 1;
        if (kb + 1 < 16) {
            LR_LOAD(s ^ 1, kb + 1);
            asm volatile("cp.async.wait_group 1;" ::: "memory");
        } else {
            CP_WAIT0();
        }
        __syncthreads();
        const uint32_t Ab = smem_u32(Ash[s]);
        const uint32_t Bb = smem_u32(Bsh[s]);
#pragma unroll
        for (int ks = 0; ks < 4; ks++) {
            unsigned af[2][4], bf[2][2];
#pragma unroll
            for (int mi = 0; mi < 2; mi++) {
                int row = wm + mi * 16 + a_row;
                ldsm_x4(af[mi][0], af[mi][1], af[mi][2], af[mi][3],
                        Ab + (uint32_t)(row * 128 + (((ks * 2 + a_kh) ^ l7) << 4)));
            }
            {
                int row = wn + b_row;
                ldsm_x4(bf[0][0], bf[0][1], bf[1][0], bf[1][1],
                        Bb + (uint32_t)(row * 128 + (((ks * 2 + b_kh) ^ l7) << 4)));
            }
#pragma unroll
            for (int mi = 0; mi < 2; mi++)
#pragma unroll
                for (int nj = 0; nj < 2; nj++) MMA_F16(acc[mi][nj], af[mi], bf[nj]);
        }
        __syncthreads();
    }

#pragma unroll
    for (int mi = 0; mi < 2; mi++) {
#pragma unroll
        for (int nj = 0; nj < 2; nj++) {
            int col = wn + nj * 8 + (kc << 1);
            size_t r0 = (size_t)(t0 + wm + mi * 16 + rr);
            *(__half2*)(tmph + r0 * RANKK + col) =
                __floats2half2_rn(acc[mi][nj][0], acc[mi][nj][1]);
            *(__half2*)(tmph + (r0 + 8) * RANKK + col) =
                __floats2half2_rn(acc[mi][nj][2], acc[mi][nj][3]);
        }
    }
}

// ============ causal scan, 3-phase chunked (fp32, exact) ============
__global__ void scanA_kernel(float* __restrict__ buf, const float* __restrict__ logA,
                             const float* __restrict__ logdt, float* __restrict__ seg) {
    int d = blockIdx.x * 32 + threadIdx.x;
    int s = blockIdx.y * 8 + threadIdx.y;
    float a = expf(-expf(logA[d]) * expf(logdt[d]));
    float y = 0.f;
    int t0 = s * SEGLEN;
#pragma unroll 8
    for (int tt = 0; tt < SEGLEN; tt++) {
        int i = (t0 + tt) * DD + d;
        y = a * y + buf[i];
        buf[i] = y;
    }
    seg[s * DD + d] = y;
}

__global__ void scanB_kernel(float* __restrict__ seg, const float* __restrict__ logA,
                             const float* __restrict__ logdt) {
    int d = blockIdx.x * 16 + threadIdx.x;
    int j = threadIdx.y;
    float a = expf(-expf(logA[d]) * expf(logdt[d]));
    float a32 = a;
#pragma unroll
    for (int q = 0; q < 5; q++) a32 *= a32;
    __shared__ float s[NSEG][17];
    float cur = seg[j * DD + d];
    s[j][threadIdx.x] = cur;
    float m = a32;
    for (int st = 1; st < NSEG; st <<= 1) {
        __syncthreads();
        float prev = (j >= st) ? s[j - st][threadIdx.x] : 0.f;
        __syncthreads();
        cur += m * prev;
        s[j][threadIdx.x] = cur;
        m = m * m;
    }
    seg[j * DD + d] = cur;
}

__global__ void scanC_kernel(float* __restrict__ buf, const float* __restrict__ logA,
                             const float* __restrict__ logdt, const float* __restrict__ seg) {
    int d = blockIdx.x * 32 + threadIdx.x;
    int s = blockIdx.y * 8 + threadIdx.y;
    if (s == 0) return;
    float a = expf(-expf(logA[d]) * expf(logdt[d]));
    float carry = seg[(s - 1) * DD + d];
    float f = a;
    int t0 = s * SEGLEN;
#pragma unroll 8
    for (int tt = 0; tt < SEGLEN; tt++) {
        int i = (t0 + tt) * DD + d;
        buf[i] += f * carry;
        f *= a;
    }
}

// ---------------- combine: hn = rmsnorm(hseq + gain*ud) -> fp16 ----------------
__global__ void combine_kernel(const float* __restrict__ h, const float* __restrict__ udep,
                               const float* __restrict__ logAd, const float* __restrict__ logdtd,
                               const int* __restrict__ pK, __half* __restrict__ hn) {
    int t = blockIdx.x;
    int tid = threadIdx.x;
    int K = *pK;
    float hv[4];
    float ss = 0.f;
#pragma unroll
    for (int r = 0; r < 4; r++) {
        int d = tid + r * 256;
        float g;
        if (d < NMEM) {
            g = (float)K;
        } else {
            float aD = expf(-expf(logAd[d - NMEM]) * expf(logdtd[d - NMEM]));
            float om = 1.f - aD;
            float safe = fmaxf(om, 1e-8f);
            float p = 1.f;
            for (int k = 0; k < K; k++) p *= aD;
            g = (fabsf(om) < 1e-6f) ? (float)K : (1.f - p) / safe;
        }
        float hx = h[t * DD + d] + g * udep[t * DD + d];
        hv[r] = hx;
        ss += hx * hx;
    }
    __shared__ float red[256];
    red[tid] = ss;
    __syncthreads();
    for (int s = 128; s > 0; s >>= 1) {
        if (tid < s) red[tid] += red[tid + s];
        __syncthreads();
    }
    float sc = rsqrtf(red[0] / (float)DD + RMS_EPS);
#pragma unroll
    for (int r = 0; r < 4; r++) {
        int d = tid + r * 256;
        hn[t * DD + d] = __float2half_rn(hv[r] * sc);
    }
}

// ======= LM head GEMM: persistent CTAs, fp16 m16n8k16, ldmatrix+SW128, 4-stage ========
#define A_ST 16384
#define B_ST 32768
#define NSTG 4
#define LM_SMEM (NSTG * (A_ST + B_ST))
#define GPERS 152
#define NTILES (16 * 197)  // (TT/128) x ceil(VV/256)

__global__ void __launch_bounds__(256, 1)
lmhead_gemm(const __half* __restrict__ A, const __half* __restrict__ B, float* __restrict__ C) {
    extern __shared__ __align__(16) char smc[];
    const uint32_t smb = smem_u32(smc);
    const int tid = threadIdx.x;
    const int lane = tid & 31;
    const int warp = tid >> 5;
    const int bid = blockIdx.x;
    const int wm = (warp >> 2) * 64;
    const int wn = (warp & 3) * 64;
    const int rr = lane >> 2;
    const int kc = lane & 3;
    const int l7 = lane & 7;

    float acc[4][8][4];
#pragma unroll
    for (int i = 0; i < 4; i++)
#pragma unroll
        for (int j = 0; j < 8; j++)
#pragma unroll
            for (int k = 0; k < 4; k++) acc[i][j][k] = 0.f;

    // chunk j -> tile tt = bid + (j>>4)*GPERS, kb = j&15, stage = j&3
#define LOAD_CHUNK(j_)                                                                 \
    {                                                                                  \
        int tt_ = bid + ((j_) >> 4) * GPERS;                                           \
        if (tt_ < NTILES) {                                                            \
            int kb_ = (j_) & 15;                                                       \
            int s_ = (j_) & 3;                                                         \
            int M0_ = (tt_ & 15) * 128;                                                \
            int N0_ = (tt_ >> 4) * 256;                                                \
            int nVal_ = (VV - N0_ < 256) ? (VV - N0_) : 256;                           \
            _Pragma("unroll") for (int i = 0; i < 4; i++) {                            \
                int cch = tid + i * 256;                                               \
                int m = cch >> 3, q = cch & 7;                                         \
                uint32_t dst = smb + s_ * A_ST + (uint32_t)(m * 128 + ((q ^ (m & 7)) << 4)); \
                cp16(dst, A + (size_t)(M0_ + m) * DD + kb_ * 64 + q * 8, 16);          \
            }                                                                          \
            _Pragma("unroll") for (int i = 0; i < 8; i++) {                            \
                int cch = tid + i * 256;                                               \
                int n = cch >> 3, q = cch & 7;                                         \
                uint32_t dst = smb + NSTG * A_ST + s_ * B_ST +                         \
                               (uint32_t)(n * 128 + ((q ^ (n & 7)) << 4));             \
                int ok = (n < nVal_);                                                  \
                cp16(dst, B + (size_t)(N0_ + (ok ? n : 0)) * DD + kb_ * 64 + q * 8,    \
                     ok ? 16 : 0);                                                     \
            }                                                                          \
        }                                                                              \
        CP_COMMIT();                                                                   \
    }

    const int myTiles = (NTILES - 1 - bid) / GPERS + 1;
    const int J = myTiles * 16;

    LOAD_CHUNK(0);
    LOAD_CHUNK(1);
    LOAD_CHUNK(2);

    const int a_row = (lane & 15);
    const int a_kh = lane >> 4;
    const int b_row = (lane & 7) + ((lane >> 4) & 1) * 8;
    const int b_kh = (lane >> 3) & 1;

    for (int j = 0; j < J; j++) {
        asm volatile("cp.async.wait_group 2;" ::: "memory");
        __syncthreads();
        LOAD_CHUNK(j + 3);

        const int s = j & 3;
        const uint32_t Ab = smb + s * A_ST;
        const uint32_t Bb = smb + NSTG * A_ST + s * B_ST;

#pragma unroll
        for (int ks = 0; ks < 4; ks++) {
            unsigned af[4][4], bf[8][2];
#pragma unroll
            for (int mi = 0; mi < 4; mi++) {
                int row = wm + mi * 16 + a_row;
                int chunk = (ks * 2 + a_kh) ^ l7;
                ldsm_x4(af[mi][0], af[mi][1], af[mi][2], af[mi][3],
                        Ab + (uint32_t)(row * 128 + (chunk << 4)));
            }
#pragma unroll
            for (int njp = 0; njp < 4; njp++) {
                int row = wn + njp * 16 + b_row;
                int chunk = (ks * 2 + b_kh) ^ l7;
                ldsm_x4(bf[2 * njp][0], bf[2 * njp][1], bf[2 * njp + 1][0], bf[2 * njp + 1][1],
                        Bb + (uint32_t)(row * 128 + (chunk << 4)));
            }
#pragma unroll
            for (int mi = 0; mi < 4; mi++)
#pragma unroll
                for (int nj = 0; nj < 8; nj++) MMA_F16(acc[mi][nj], af[mi], bf[nj]);
        }

        if ((j & 15) == 15) {
            // epilogue for tile
            int tt = bid + (j >> 4) * GPERS;
            int M0 = (tt & 15) * 128;
            int N0 = (tt >> 4) * 256;
#pragma unroll
            for (int mi = 0; mi < 4; mi++) {
#pragma unroll
                for (int nj = 0; nj < 8; nj++) {
                    int c0 = N0 + wn + nj * 8 + (kc << 1);
                    if (c0 < VV) {
                        size_t r0 = (size_t)(M0 + wm + mi * 16 + rr);
                        __stcs((float2*)(C + r0 * VV + c0),
                               make_float2(acc[mi][nj][0] * BSCALE_INV,
                                           acc[mi][nj][1] * BSCALE_INV));
                        __stcs((float2*)(C + (r0 + 8) * VV + c0),
                               make_float2(acc[mi][nj][2] * BSCALE_INV,
                                           acc[mi][nj][3] * BSCALE_INV));
                    }
#pragma unroll
                    for (int k = 0; k < 4; k++) acc[mi][nj][k] = 0.f;
                }
            }
        }
    }
}

// ---------------- launcher ----------------
extern "C" void kernel_launch(void* const* d_in, const int* in_sizes, int n_in,
                              void* d_out, int out_size) {
    const int* idx = (const int*)d_in[0];
    const int* pK = (const int*)d_in[1];
    const float* wte = (const float*)d_in[2];
    const float* wpe = (const float*)d_in[3];
    const float* bseq_w = (const float*)d_in[4];
    const float* logA_seq = (const float*)d_in[5];
    const float* logdt_seq = (const float*)d_in[6];
    const float* bdepth_w = (const float*)d_in[7];
    const float* logA_depth = (const float*)d_in[8];
    const float* logdt_depth = (const float*)d_in[9];
    const float* wpost_w = (const float*)d_in[10];
    const float* wlocal_w = (const float*)d_in[11];
    const float* lowA = (const float*)d_in[12];
    const float* lowB = (const float*)d_in[13];
    const float* lm_head_w = (const float*)d_in[14];
    float* out = (float*)d_out;

    float *x, *h, *ud, *seg;
    __half *eh, *hn, *rh, *tmph, *xh, *Bh;
    __half *bseqh, *bdeph, *wposth, *wloch, *lowAh, *lowBh;
    cudaGetSymbolAddress((void**)&x, g_x);
    cudaGetSymbolAddress((void**)&h, g_h);
    cudaGetSymbolAddress((void**)&ud, g_ud);
    cudaGetSymbolAddress((void**)&seg, g_seg);
    cudaGetSymbolAddress((void**)&eh, g_eh);
    cudaGetSymbolAddress((void**)&hn, g_hn);
    cudaGetSymbolAddress((void**)&rh, g_rh);
    cudaGetSymbolAddress((void**)&tmph, g_tmph);
    cudaGetSymbolAddress((void**)&xh, g_xh);
    cudaGetSymbolAddress((void**)&Bh, g_Bh);
    cudaGetSymbolAddress((void**)&bseqh, g_bseqh);
    cudaGetSymbolAddress((void**)&bdeph, g_bdeph);
    cudaGetSymbolAddress((void**)&wposth, g_wposth);
    cudaGetSymbolAddress((void**)&wloch, g_wloch);
    cudaGetSymbolAddress((void**)&lowAh, g_lowAh);
    cudaGetSymbolAddress((void**)&lowBh, g_lowBh);

    cudaFuncSetAttribute(lmhead_gemm, cudaFuncAttributeMaxDynamicSharedMemorySize, LM_SMEM);
    cudaFuncSetAttribute(bd192_f16_kernel, cudaFuncAttributeMaxDynamicSharedMemorySize, BD192_SMEM);

    // weight conversions
    f16_convert_kernel<<<(VV * DD / 8) / 256, 256>>>(lm_head_w, Bh);
    conv5_f16_kernel<<<dim3(LYR * NBLK * 64 * 64 / 8 / 256, 5), 256>>>(
        bseq_w, bseqh, bdepth_w, bdeph, wlocal_w, wloch, lowA, lowAh, lowB, lowBh);
    conv_f16_kernel<<<LYR * NBLK * 64 * 192 / 8 / 256, 256>>>(wpost_w, wposth);

    embed_kernel<<<TT, 256>>>(idx, wte, wpe, x);

    for (int l = 0; l < LYR; l++) {
        const __half* bseq_l = bseqh + l * NBLK * 64 * 64;
        const __half* bdep_l = bdeph + l * NBLK * 64 * 64;
        const __half* wpost_l = wposth + l * NBLK * 64 * 192;
        const __half* wlocal_l = wloch + l * NBLK * 64 * 64;
        const __half* lowA_l = lowAh + l * DD * RANKK;
        const __half* lowB_l = lowBh + l * RANKK * HH;
        const float* lAs = logA_seq + l * HH;
        const float* lDs = logdt_seq + l * HH;
        const float* lAd = logA_depth + l * (HH - NMEM);
        const float* lDd = logdt_depth + l * (HH - NMEM);

        rmsnorm_f16_kernel<<<TT, 256>>>(x, eh);
        bd64_f16_kernel<<<dim3(TT / 128, NBLK), 256>>>(eh, bseq_l, bdep_l, h, ud);
        scanA_kernel<<<dim3(32, 8), dim3(32, 8)>>>(h, lAs, lDs, seg);
        scanB_kernel<<<DD / 16, dim3(16, NSEG)>>>(seg, lAs, lDs);
        scanC_kernel<<<dim3(32, 8), dim3(32, 8)>>>(h, lAs, lDs, seg);
        combine_kernel<<<TT, 256>>>(h, ud, lAd, lDd, pK, hn);
        bd192_f16_kernel<<<dim3(TT / 128, NBLK), 256, BD192_SMEM>>>(hn, eh, wpost_l, rh);
        lowrank1_f16_kernel<<<TT / 64, 256>>>(rh, lowB_l, tmph);
        update_f16_kernel<<<dim3(TT / 128, NBLK), 256>>>(x, rh, tmph, wlocal_l, lowA_l);
    }

    rmsnorm_f16_kernel<<<TT, 256>>>(x, xh);
    lmhead_gemm<<<GPERS, 256, LM_SMEM>>>(xh, Bh, out);
}

// round 17
// speedup vs baseline: 1.6132x; 1.0235x over previous
#include <cuda_runtime.h>
#include <cuda_bf16.h>
#include <cuda_fp16.h>
#include <math.h>
#include <stdint.h>

#define TT 2048
#define DD 1024
#define HH 1024
#define NBLK 16
#define LYR 4
#define RANKK 64
#define NMEM 64
#define VV 50304
#define RMS_EPS 1.1920929e-7f
#define BSCALE 1024.0f
#define BSCALE_INV 0.0009765625f
// fused scan: 128 segments of 16
#define SEG2 16
#define NSEG2 128

// ---------------- scratch ----------------
__device__ float g_x[TT * DD];
__device__ float g_h[TT * DD];
__device__ float g_ud[TT * DD];
__device__ __half g_eh[TT * DD];
__device__ __half g_hn[TT * DD];
__device__ __half g_rh[TT * HH];
__device__ __half g_tmph[TT * RANKK];
__device__ __half g_xh[TT * DD];
__device__ __half g_Bh[(size_t)VV * DD];
__device__ __half g_bseqh[LYR * NBLK * 64 * 64];
__device__ __half g_bdeph[LYR * NBLK * 64 * 64];
__device__ __half g_wposth[LYR * NBLK * 64 * 192];
__device__ __half g_wloch[LYR * NBLK * 64 * 64];
__device__ __half g_lowAh[LYR * DD * RANKK];
__device__ __half g_lowBh[LYR * RANKK * HH];

// ---------------- helpers ----------------
__device__ __forceinline__ float silu_f(float x) { return x / (1.0f + expf(-x)); }

__device__ __forceinline__ uint32_t smem_u32(const void* p) {
    uint32_t a;
    asm("{ .reg .u64 t; cvta.to.shared.u64 t, %1; cvt.u32.u64 %0, t; }" : "=r"(a) : "l"(p));
    return a;
}
__device__ __forceinline__ void cp16(uint32_t dst, const void* src, int sz) {
    asm volatile("cp.async.cg.shared.global [%0], [%1], 16, %2;"
                 :: "r"(dst), "l"(src), "r"(sz) : "memory");
}
#define CP_COMMIT() asm volatile("cp.async.commit_group;" ::: "memory")
#define CP_WAIT0() asm volatile("cp.async.wait_group 0;" ::: "memory")

__device__ __forceinline__ void ldsm_x4(unsigned& r0, unsigned& r1, unsigned& r2, unsigned& r3,
                                        uint32_t addr) {
    asm volatile("ldmatrix.sync.aligned.m8n8.x4.shared.b16 {%0,%1,%2,%3}, [%4];"
                 : "=r"(r0), "=r"(r1), "=r"(r2), "=r"(r3) : "r"(addr));
}

#define MMA_F16(c, a, b)                                                               \
    asm volatile(                                                                      \
        "mma.sync.aligned.m16n8k16.row.col.f32.f16.f16.f32 "                           \
        "{%0,%1,%2,%3},{%4,%5,%6,%7},{%8,%9},{%0,%1,%2,%3};\n"                         \
        : "+f"(c[0]), "+f"(c[1]), "+f"(c[2]), "+f"(c[3])                               \
        : "r"(a[0]), "r"(a[1]), "r"(a[2]), "r"(a[3]), "r"(b[0]), "r"(b[1]))

__device__ __forceinline__ uint32_t sw_off(int row, int q) {
    return (uint32_t)(row * 128 + ((q ^ (row & 7)) << 4));
}

// ---------------- embedding ----------------
__global__ void embed_kernel(const int* __restrict__ idx, const float* __restrict__ wte,
                             const float* __restrict__ wpe, float* __restrict__ x) {
    int t = blockIdx.x;
    int row = idx[t];
    const float4* wrow = (const float4*)(wte + (long)row * DD);
    const float4* prow = (const float4*)(wpe + (long)t * DD);
    float4* xo = (float4*)(x + t * DD);
    for (int d = threadIdx.x; d < DD / 4; d += blockDim.x) {
        float4 a = wrow[d], b = prow[d];
        xo[d] = make_float4(a.x + b.x, a.y + b.y, a.z + b.z, a.w + b.w);
    }
}

// ---------------- rmsnorm -> fp16 ----------------
__global__ void rmsnorm_f16_kernel(const float* __restrict__ in, __half* __restrict__ out) {
    int t = blockIdx.x;
    int tid = threadIdx.x;
    float4 v = ((const float4*)(in + t * DD))[tid];
    float ss = v.x * v.x + v.y * v.y + v.z * v.z + v.w * v.w;
    __shared__ float red[256];
    red[tid] = ss;
    __syncthreads();
    for (int s = 128; s > 0; s >>= 1) {
        if (tid < s) red[tid] += red[tid + s];
        __syncthreads();
    }
    float sc = rsqrtf(red[0] / (float)DD + RMS_EPS);
    __half2 h0 = __floats2half2_rn(v.x * sc, v.y * sc);
    __half2 h1 = __floats2half2_rn(v.z * sc, v.w * sc);
    ((__half2*)(out + t * DD))[tid * 2] = h0;
    ((__half2*)(out + t * DD))[tid * 2 + 1] = h1;
}

// lm_head weights: *1024, fp16
__global__ void f16_convert_kernel(const float* __restrict__ in, __half* __restrict__ out,
                                   int ngroups) {
    for (int i = blockIdx.x * blockDim.x + threadIdx.x; i < ngroups;
         i += gridDim.x * blockDim.x) {
        const float4* in4 = (const float4*)in + (size_t)i * 2;
        float4 a = in4[0], b = in4[1];
        __half h[8];
        h[0] = __float2half_rn(a.x * BSCALE); h[1] = __float2half_rn(a.y * BSCALE);
        h[2] = __float2half_rn(a.z * BSCALE); h[3] = __float2half_rn(a.w * BSCALE);
        h[4] = __float2half_rn(b.x * BSCALE); h[5] = __float2half_rn(b.y * BSCALE);
        h[6] = __float2half_rn(b.z * BSCALE); h[7] = __float2half_rn(b.w * BSCALE);
        ((uint4*)(out + (size_t)i * 8))[0] = *(uint4*)&h[0];
    }
}

// convert 5 equal-size fp32 arrays -> fp16 (blockIdx.y selects array)
__global__ void conv5_f16_kernel(const float* __restrict__ p0, __half* __restrict__ q0,
                                 const float* __restrict__ p1, __half* __restrict__ q1,
                                 const float* __restrict__ p2, __half* __restrict__ q2,
                                 const float* __restrict__ p3, __half* __restrict__ q3,
                                 const float* __restrict__ p4, __half* __restrict__ q4) {
    const float* in;
    __half* out;
    switch (blockIdx.y) {
        case 0: in = p0; out = q0; break;
        case 1: in = p1; out = q1; break;
        case 2: in = p2; out = q2; break;
        case 3: in = p3; out = q3; break;
        default: in = p4; out = q4; break;
    }
    size_t i = (size_t)blockIdx.x * blockDim.x + threadIdx.x;
    const float4* in4 = (const float4*)in + i * 2;
    float4 a = in4[0], b = in4[1];
    __half h[8];
    h[0] = __float2half_rn(a.x); h[1] = __float2half_rn(a.y);
    h[2] = __float2half_rn(a.z); h[3] = __float2half_rn(a.w);
    h[4] = __float2half_rn(b.x); h[5] = __float2half_rn(b.y);
    h[6] = __float2half_rn(b.z); h[7] = __float2half_rn(b.w);
    ((uint4*)(out + i * 8))[0] = *(uint4*)&h[0];
}

__global__ void conv_f16_kernel(const float* __restrict__ in, __half* __restrict__ out) {
    size_t i = (size_t)blockIdx.x * blockDim.x + threadIdx.x;
    const float4* in4 = (const float4*)in + i * 2;
    float4 a = in4[0], b = in4[1];
    __half h[8];
    h[0] = __float2half_rn(a.x); h[1] = __float2half_rn(a.y);
    h[2] = __float2half_rn(a.z); h[3] = __float2half_rn(a.w);
    h[4] = __float2half_rn(b.x); h[5] = __float2half_rn(b.y);
    h[6] = __float2half_rn(b.z); h[7] = __float2half_rn(b.w);
    ((uint4*)(out + i * 8))[0] = *(uint4*)&h[0];
}

// ======== bd64 dual: h=silu(e@W1^T), ud=silu(e@W2^T). M=128, N=128(W1|W2), K=64 =========
__global__ void __launch_bounds__(256)
bd64_f16_kernel(const __half* __restrict__ eh, const __half* __restrict__ W1h,
                const __half* __restrict__ W2h, float* __restrict__ h, float* __restrict__ ud) {
    __shared__ __half Ash[128 * 64];
    __shared__ __half Bsh[128 * 64];
    const int t0 = blockIdx.x * 128;
    const int n = blockIdx.y;
    const int tid = threadIdx.x;
    const int lane = tid & 31;
    const int warp = tid >> 5;
    const uint32_t Ab = smem_u32(Ash), Bb = smem_u32(Bsh);
    const int wm = (warp >> 1) * 32;
    const int wn = (warp & 1) * 64;
    const int rr = lane >> 2, kc = lane & 3, l7 = lane & 7;

#pragma unroll
    for (int i = 0; i < 4; i++) {
        int cch = tid + i * 256;
        int m = cch >> 3, q = cch & 7;
        cp16(Ab + sw_off(m, q), eh + (size_t)(t0 + m) * DD + n * 64 + q * 8, 16);
        const __half* wsrc = (m < 64) ? (W1h + (n * 64 + m) * 64 + q * 8)
                                      : (W2h + (n * 64 + m - 64) * 64 + q * 8);
        cp16(Bb + sw_off(m, q), wsrc, 16);
    }
    CP_COMMIT();
    CP_WAIT0();
    __syncthreads();

    float acc[2][8][4];
#pragma unroll
    for (int a = 0; a < 2; a++)
#pragma unroll
        for (int b = 0; b < 8; b++)
#pragma unroll
            for (int c = 0; c < 4; c++) acc[a][b][c] = 0.f;

    const int a_row = lane & 15, a_kh = lane >> 4;
    const int b_row = (lane & 7) + ((lane >> 4) & 1) * 8;
    const int b_kh = (lane >> 3) & 1;

#pragma unroll
    for (int ks = 0; ks < 4; ks++) {
        unsigned af[2][4], bf[8][2];
#pragma unroll
        for (int mi = 0; mi < 2; mi++) {
            int row = wm + mi * 16 + a_row;
            ldsm_x4(af[mi][0], af[mi][1], af[mi][2], af[mi][3],
                    Ab + (uint32_t)(row * 128 + (((ks * 2 + a_kh) ^ l7) << 4)));
        }
#pragma unroll
        for (int njp = 0; njp < 4; njp++) {
            int row = wn + njp * 16 + b_row;
            ldsm_x4(bf[2 * njp][0], bf[2 * njp][1], bf[2 * njp + 1][0], bf[2 * njp + 1][1],
                    Bb + (uint32_t)(row * 128 + (((ks * 2 + b_kh) ^ l7) << 4)));
        }
#pragma unroll
        for (int mi = 0; mi < 2; mi++)
#pragma unroll
            for (int nj = 0; nj < 8; nj++) MMA_F16(acc[mi][nj], af[mi], bf[nj]);
    }

    float* outp = (wn == 0) ? h : ud;
#pragma unroll
    for (int mi = 0; mi < 2; mi++) {
#pragma unroll
        for (int nj = 0; nj < 8; nj++) {
            int col = n * 64 + nj * 8 + (kc << 1);
            size_t r0 = (size_t)(t0 + wm + mi * 16 + rr);
            *(float2*)(outp + r0 * DD + col) =
                make_float2(silu_f(acc[mi][nj][0]), silu_f(acc[mi][nj][1]));
            *(float2*)(outp + (r0 + 8) * DD + col) =
                make_float2(silu_f(acc[mi][nj][2]), silu_f(acc[mi][nj][3]));
        }
    }
}

// ======== bd192: r = silu(concat @ wpost^T), virtual concat, fp16 out ========
#define BD192_SMEM (3 * 16384 + 3 * 8192)
__global__ void __launch_bounds__(256)
bd192_f16_kernel(const __half* __restrict__ hn, const __half* __restrict__ eh,
                 const __half* __restrict__ Wh, __half* __restrict__ rh) {
    extern __shared__ __align__(16) char smc[];
    const uint32_t Ab = smem_u32(smc);
    const uint32_t Bb = Ab + 3 * 16384;
    const int t0 = blockIdx.x * 128;
    const int n = blockIdx.y;
    const int tid = threadIdx.x;
    const int lane = tid & 31;
    const int warp = tid >> 5;
    const int wm = (warp >> 1) * 32;
    const int wn = (warp & 1) * 32;
    const int rr = lane >> 2, kc = lane & 3, l7 = lane & 7;

#pragma unroll
    for (int c = 0; c < 3; c++) {
        const int pc = 3 * n + c;
        const int part = pc >> 4;
        const int colo = (pc & 15) << 6;
#pragma unroll
        for (int i = 0; i < 4; i++) {
            int cch = tid + i * 256;
            int m = cch >> 3, q = cch & 7;
            int trow = t0 + m;
            uint32_t dst = Ab + c * 16384 + sw_off(m, q);
            if (part == 0) {
                cp16(dst, hn + (size_t)trow * DD + colo + q * 8, 16);
            } else if (part == 1) {
                cp16(dst, eh + (size_t)trow * DD + colo + q * 8, 16);
            } else {
                const __half* src = eh + (size_t)(trow - 1) * DD + colo + q * 8;
                cp16(dst, (trow == 0) ? (const __half*)eh : src, (trow == 0) ? 0 : 16);
            }
        }
#pragma unroll
        for (int i = 0; i < 2; i++) {
            int cch = tid + i * 256;
            int o = cch >> 3, q = cch & 7;
            cp16(Bb + c * 8192 + sw_off(o, q), Wh + (size_t)(n * 64 + o) * 192 + c * 64 + q * 8, 16);
        }
    }
    CP_COMMIT();
    CP_WAIT0();
    __syncthreads();

    float acc[2][4][4];
#pragma unroll
    for (int a = 0; a < 2; a++)
#pragma unroll
        for (int b = 0; b < 4; b++)
#pragma unroll
            for (int c = 0; c < 4; c++) acc[a][b][c] = 0.f;

    const int a_row = lane & 15, a_kh = lane >> 4;
    const int b_row = (lane & 7) + ((lane >> 4) & 1) * 8;
    const int b_kh = (lane >> 3) & 1;

#pragma unroll
    for (int ks = 0; ks < 12; ks++) {
        const int c = ks >> 2, ksl = ks & 3;
        unsigned af[2][4], bf[4][2];
#pragma unroll
        for (int mi = 0; mi < 2; mi++) {
            int row = wm + mi * 16 + a_row;
            ldsm_x4(af[mi][0], af[mi][1], af[mi][2], af[mi][3],
                    Ab + c * 16384 + (uint32_t)(row * 128 + (((ksl * 2 + a_kh) ^ l7) << 4)));
        }
#pragma unroll
        for (int njp = 0; njp < 2; njp++) {
            int row = wn + njp * 16 + b_row;
            ldsm_x4(bf[2 * njp][0], bf[2 * njp][1], bf[2 * njp + 1][0], bf[2 * njp + 1][1],
                    Bb + c * 8192 + (uint32_t)(row * 128 + (((ksl * 2 + b_kh) ^ l7) << 4)));
        }
#pragma unroll
        for (int mi = 0; mi < 2; mi++)
#pragma unroll
            for (int nj = 0; nj < 4; nj++) MMA_F16(acc[mi][nj], af[mi], bf[nj]);
    }

#pragma unroll
    for (int mi = 0; mi < 2; mi++) {
#pragma unroll
        for (int nj = 0; nj < 4; nj++) {
            int col = n * 64 + wn + nj * 8 + (kc << 1);
            size_t r0 = (size_t)(t0 + wm + mi * 16 + rr);
            *(__half2*)(rh + r0 * HH + col) =
                __floats2half2_rn(silu_f(acc[mi][nj][0]), silu_f(acc[mi][nj][1]));
            *(__half2*)(rh + (r0 + 8) * HH + col) =
                __floats2half2_rn(silu_f(acc[mi][nj][2]), silu_f(acc[mi][nj][3]));
        }
    }
}

// ======== update: x += rh@wlocal^T + tmp@lowA^T ========
__global__ void __launch_bounds__(256)
update_f16_kernel(float* __restrict__ x, const __half* __restrict__ rh,
                  const __half* __restrict__ tmph, const __half* __restrict__ wloc,
                  const __half* __restrict__ lowA) {
    __shared__ __half Ash[2][128 * 64];
    __shared__ __half Bsh[2][64 * 64];
    const int t0 = blockIdx.x * 128;
    const int n = blockIdx.y;
    const int tid = threadIdx.x;
    const int lane = tid & 31;
    const int warp = tid >> 5;
    const uint32_t Ab0 = smem_u32(Ash[0]), Ab1 = smem_u32(Ash[1]);
    const uint32_t Bb0 = smem_u32(Bsh[0]), Bb1 = smem_u32(Bsh[1]);
    const int wm = (warp >> 1) * 32;
    const int wn = (warp & 1) * 32;
    const int rr = lane >> 2, kc = lane & 3, l7 = lane & 7;

#pragma unroll
    for (int i = 0; i < 4; i++) {
        int cch = tid + i * 256;
        int m = cch >> 3, q = cch & 7;
        cp16(Ab0 + sw_off(m, q), rh + (size_t)(t0 + m) * HH + n * 64 + q * 8, 16);
        cp16(Ab1 + sw_off(m, q), tmph + (size_t)(t0 + m) * RANKK + q * 8, 16);
    }
#pragma unroll
    for (int i = 0; i < 2; i++) {
        int cch = tid + i * 256;
        int o = cch >> 3, q = cch & 7;
        cp16(Bb0 + sw_off(o, q), wloc + (size_t)(n * 64 + o) * 64 + q * 8, 16);
        cp16(Bb1 + sw_off(o, q), lowA + (size_t)(n * 64 + o) * RANKK + q * 8, 16);
    }
    CP_COMMIT();
    CP_WAIT0();
    __syncthreads();

    float acc[2][4][4];
#pragma unroll
    for (int a = 0; a < 2; a++)
#pragma unroll
        for (int b = 0; b < 4; b++)
#pragma unroll
            for (int c = 0; c < 4; c++) acc[a][b][c] = 0.f;

    const int a_row = lane & 15, a_kh = lane >> 4;
    const int b_row = (lane & 7) + ((lane >> 4) & 1) * 8;
    const int b_kh = (lane >> 3) & 1;

#pragma unroll
    for (int ks = 0; ks < 8; ks++) {
        const int ph = ks >> 2, ksl = ks & 3;
        const uint32_t Ab = ph ? Ab1 : Ab0;
        const uint32_t Bb = ph ? Bb1 : Bb0;
        unsigned af[2][4], bf[4][2];
#pragma unroll
        for (int mi = 0; mi < 2; mi++) {
            int row = wm + mi * 16 + a_row;
            ldsm_x4(af[mi][0], af[mi][1], af[mi][2], af[mi][3],
                    Ab + (uint32_t)(row * 128 + (((ksl * 2 + a_kh) ^ l7) << 4)));
        }
#pragma unroll
        for (int njp = 0; njp < 2; njp++) {
            int row = wn + njp * 16 + b_row;
            ldsm_x4(bf[2 * njp][0], bf[2 * njp][1], bf[2 * njp + 1][0], bf[2 * njp + 1][1],
                    Bb + (uint32_t)(row * 128 + (((ksl * 2 + b_kh) ^ l7) << 4)));
        }
#pragma unroll
        for (int mi = 0; mi < 2; mi++)
#pragma unroll
            for (int nj = 0; nj < 4; nj++) MMA_F16(acc[mi][nj], af[mi], bf[nj]);
    }

#pragma unroll
    for (int mi = 0; mi < 2; mi++) {
#pragma unroll
        for (int nj = 0; nj < 4; nj++) {
            int col = n * 64 + wn + nj * 8 + (kc << 1);
            size_t r0 = (size_t)(t0 + wm + mi * 16 + rr);
            float2* p0 = (float2*)(x + r0 * DD + col);
            float2 v0 = *p0;
            v0.x += acc[mi][nj][0]; v0.y += acc[mi][nj][1];
            *p0 = v0;
            float2* p1 = (float2*)(x + (r0 + 8) * DD + col);
            float2 v1 = *p1;
            v1.x += acc[mi][nj][2]; v1.y += acc[mi][nj][3];
            *p1 = v1;
        }
    }
}

// ======== lowrank1: tmp = rh @ lowB^T ========
__global__ void __launch_bounds__(256)
lowrank1_f16_kernel(const __half* __restrict__ rh, const __half* __restrict__ lowB,
                    __half* __restrict__ tmph) {
    __shared__ __half Ash[2][64 * 64];
    __shared__ __half Bsh[2][64 * 64];
    const int t0 = blockIdx.x * 64;
    const int tid = threadIdx.x;
    const int lane = tid & 31;
    const int warp = tid >> 5;
    const int wm = (warp >> 2) * 32;
    const int wn = (warp & 3) * 16;
    const int rr = lane >> 2, kc = lane & 3, l7 = lane & 7;

#define LR_LOAD(s, kb)                                                                   \
    {                                                                                    \
        _Pragma("unroll") for (int i = 0; i < 2; i++) {                                  \
            int cch = tid + i * 256;                                                     \
            int m = cch >> 3, q = cch & 7;                                               \
            cp16(smem_u32(Ash[s]) + sw_off(m, q),                                        \
                 rh + (size_t)(t0 + m) * HH + (kb) * 64 + q * 8, 16);                    \
            cp16(smem_u32(Bsh[s]) + sw_off(m, q),                                        \
                 lowB + (size_t)m * HH + (kb) * 64 + q * 8, 16);                         \
        }                                                                                \
        CP_COMMIT();                                                                     \
    }

    float acc[2][2][4];
#pragma unroll
    for (int a = 0; a < 2; a++)
#pragma unroll
        for (int b = 0; b < 2; b++)
#pragma unroll
            for (int c = 0; c < 4; c++) acc[a][b][c] = 0.f;

    const int a_row = lane & 15, a_kh = lane >> 4;
    const int b_row = (lane & 7) + ((lane >> 4) & 1) * 8;
    const int b_kh = (lane >> 3) & 1;

    LR_LOAD(0, 0);
    for (int kb = 0; kb < 16; kb++) {
        const int s = kb & 1;
        if (kb + 1 < 16) {
            LR_LOAD(s ^ 1, kb + 1);
            asm volatile("cp.async.wait_group 1;" ::: "memory");
        } else {
            CP_WAIT0();
        }
        __syncthreads();
        const uint32_t Ab = smem_u32(Ash[s]);
        const uint32_t Bb = smem_u32(Bsh[s]);
#pragma unroll
        for (int ks = 0; ks < 4; ks++) {
            unsigned af[2][4], bf[2][2];
#pragma unroll
            for (int mi = 0; mi < 2; mi++) {
                int row = wm + mi * 16 + a_row;
                ldsm_x4(af[mi][0], af[mi][1], af[mi][2], af[mi][3],
                        Ab + (uint32_t)(row * 128 + (((ks * 2 + a_kh) ^ l7) << 4)));
            }
            {
                int row = wn + b_row;
                ldsm_x4(bf[0][0], bf[0][1], bf[1][0], bf[1][1],
                        Bb + (uint32_t)(row * 128 + (((ks * 2 + b_kh) ^ l7) << 4)));
            }
#pragma unroll
            for (int mi = 0; mi < 2; mi++)
#pragma unroll
                for (int nj = 0; nj < 2; nj++) MMA_F16(acc[mi][nj], af[mi], bf[nj]);
        }
        __syncthreads();
    }

#pragma unroll
    for (int mi = 0; mi < 2; mi++) {
#pragma unroll
        for (int nj = 0; nj < 2; nj++) {
            int col = wn + nj * 8 + (kc << 1);
            size_t r0 = (size_t)(t0 + wm + mi * 16 + rr);
            *(__half2*)(tmph + r0 * RANKK + col) =
                __floats2half2_rn(acc[mi][nj][0], acc[mi][nj][1]);
            *(__half2*)(tmph + (r0 + 8) * RANKK + col) =
                __floats2half2_rn(acc[mi][nj][2], acc[mi][nj][3]);
        }
    }
}

// ============ fused causal scan: one kernel, in-block Kogge-Stone ============
// grid DD/8=128, block (8 d, 128 seg). SEG2=16 timesteps per thread.
__global__ void __launch_bounds__(1024)
scan_fused_kernel(float* __restrict__ buf, const float* __restrict__ logA,
                  const float* __restrict__ logdt) {
    const int d = blockIdx.x * 8 + threadIdx.x;
    const int j = threadIdx.y;
    const float a = expf(-expf(logA[d]) * expf(logdt[d]));
    const int t0 = j * SEG2;

    // pass 1: local scan, keep values in registers
    float v[SEG2];
    float y = 0.f;
#pragma unroll
    for (int tt = 0; tt < SEG2; tt++) {
        y = a * y + buf[(t0 + tt) * DD + d];
        v[tt] = y;
    }

    // Kogge-Stone over 128 segments (ratio a^16)
    __shared__ float s[NSEG2][9];
    float a16 = a;
#pragma unroll
    for (int q = 0; q < 4; q++) a16 *= a16;
    float cur = y;
    float m = a16;
    s[j][threadIdx.x] = cur;
#pragma unroll
    for (int st = 1; st < NSEG2; st <<= 1) {
        __syncthreads();
        float prev = (j >= st) ? s[j - st][threadIdx.x] : 0.f;
        __syncthreads();
        cur += m * prev;
        s[j][threadIdx.x] = cur;
        m = m * m;
    }
    __syncthreads();

    // pass 2: add decayed carry, write back
    float carry = (j > 0) ? s[j - 1][threadIdx.x] : 0.f;
    float f = a;
#pragma unroll
    for (int tt = 0; tt < SEG2; tt++) {
        buf[(t0 + tt) * DD + d] = v[tt] + f * carry;
        f *= a;
    }
}

// ---------------- combine: hn = rmsnorm(hseq + gain*ud) -> fp16 ----------------
__global__ void combine_kernel(const float* __restrict__ h, const float* __restrict__ udep,
                               const float* __restrict__ logAd, const float* __restrict__ logdtd,
                               const int* __restrict__ pK, __half* __restrict__ hn) {
    int t = blockIdx.x;
    int tid = threadIdx.x;
    int K = *pK;
    float hv[4];
    float ss = 0.f;
#pragma unroll
    for (int r = 0; r < 4; r++) {
        int d = tid + r * 256;
        float g;
        if (d < NMEM) {
            g = (float)K;
        } else {
            float aD = expf(-expf(logAd[d - NMEM]) * expf(logdtd[d - NMEM]));
            float om = 1.f - aD;
            float safe = fmaxf(om, 1e-8f);
            float p = 1.f;
            for (int k = 0; k < K; k++) p *= aD;
            g = (fabsf(om) < 1e-6f) ? (float)K : (1.f - p) / safe;
        }
        float hx = h[t * DD + d] + g * udep[t * DD + d];
        hv[r] = hx;
        ss += hx * hx;
    }
    __shared__ float red[256];
    red[tid] = ss;
    __syncthreads();
    for (int s = 128; s > 0; s >>= 1) {
        if (tid < s) red[tid] += red[tid + s];
        __syncthreads();
    }
    float sc = rsqrtf(red[0] / (float)DD + RMS_EPS);
#pragma unroll
    for (int r = 0; r < 4; r++) {
        int d = tid + r * 256;
        hn[t * DD + d] = __float2half_rn(hv[r] * sc);
    }
}

// ======= LM head GEMM: persistent CTAs, fp16 m16n8k16, ldmatrix+SW128, 4-stage ========
#define A_ST 16384
#define B_ST 32768
#define NSTG 4
#define LM_SMEM (NSTG * (A_ST + B_ST))
#define GPERS 152
#define NTILES (16 * 197)

__global__ void __launch_bounds__(256, 1)
lmhead_gemm(const __half* __restrict__ A, const __half* __restrict__ B, float* __restrict__ C) {
    extern __shared__ __align__(16) char smc[];
    const uint32_t smb = smem_u32(smc);
    const int tid = threadIdx.x;
    const int lane = tid & 31;
    const int warp = tid >> 5;
    const int bid = blockIdx.x;
    const int wm = (warp >> 2) * 64;
    const int wn = (warp & 3) * 64;
    const int rr = lane >> 2;
    const int kc = lane & 3;
    const int l7 = lane & 7;

    float acc[4][8][4];
#pragma unroll
    for (int i = 0; i < 4; i++)
#pragma unroll
        for (int j = 0; j < 8; j++)
#pragma unroll
            for (int k = 0; k < 4; k++) acc[i][j][k] = 0.f;

#define LOAD_CHUNK(j_)                                                                 \
    {                                                                                  \
        int tt_ = bid + ((j_) >> 4) * GPERS;                                           \
        if (tt_ < NTILES) {                                                            \
            int kb_ = (j_) & 15;                                                       \
            int s_ = (j_) & 3;                                                         \
            int M0_ = (tt_ & 15) * 128;                                                \
            int N0_ = (tt_ >> 4) * 256;                                                \
            int nVal_ = (VV - N0_ < 256) ? (VV - N0_) : 256;                           \
            _Pragma("unroll") for (int i = 0; i < 4; i++) {                            \
                int cch = tid + i * 256;                                               \
                int m = cch >> 3, q = cch & 7;                                         \
                uint32_t dst = smb + s_ * A_ST + (uint32_t)(m * 128 + ((q ^ (m & 7)) << 4)); \
                cp16(dst, A + (size_t)(M0_ + m) * DD + kb_ * 64 + q * 8, 16);          \
            }                                                                          \
            _Pragma("unroll") for (int i = 0; i < 8; i++) {                            \
                int cch = tid + i * 256;                                               \
                int n = cch >> 3, q = cch & 7;                                         \
                uint32_t dst = smb + NSTG * A_ST + s_ * B_ST +                         \
                               (uint32_t)(n * 128 + ((q ^ (n & 7)) << 4));             \
                int ok = (n < nVal_);                                                  \
                cp16(dst, B + (size_t)(N0_ + (ok ? n : 0)) * DD + kb_ * 64 + q * 8,    \
                     ok ? 16 : 0);                                                     \
            }                                                                          \
        }                                                                              \
        CP_COMMIT();                                                                   \
    }

    const int myTiles = (NTILES - 1 - bid) / GPERS + 1;
    const int J = myTiles * 16;

    LOAD_CHUNK(0);
    LOAD_CHUNK(1);
    LOAD_CHUNK(2);

    const int a_row = (lane & 15);
    const int a_kh = lane >> 4;
    const int b_row = (lane & 7) + ((lane >> 4) & 1) * 8;
    const int b_kh = (lane >> 3) & 1;

    for (int j = 0; j < J; j++) {
        asm volatile("cp.async.wait_group 2;" ::: "memory");
        __syncthreads();
        LOAD_CHUNK(j + 3);

        const int s = j & 3;
        const uint32_t Ab = smb + s * A_ST;
        const uint32_t Bb = smb + NSTG * A_ST + s * B_ST;

#pragma unroll
        for (int ks = 0; ks < 4; ks++) {
            unsigned af[4][4], bf[8][2];
#pragma unroll
            for (int mi = 0; mi < 4; mi++) {
                int row = wm + mi * 16 + a_row;
                int chunk = (ks * 2 + a_kh) ^ l7;
                ldsm_x4(af[mi][0], af[mi][1], af[mi][2], af[mi][3],
                        Ab + (uint32_t)(row * 128 + (chunk << 4)));
            }
#pragma unroll
            for (int njp = 0; njp < 4; njp++) {
                int row = wn + njp * 16 + b_row;
                int chunk = (ks * 2 + b_kh) ^ l7;
                ldsm_x4(bf[2 * njp][0], bf[2 * njp][1], bf[2 * njp + 1][0], bf[2 * njp + 1][1],
                        Bb + (uint32_t)(row * 128 + (chunk << 4)));
            }
#pragma unroll
            for (int mi = 0; mi < 4; mi++)
#pragma unroll
                for (int nj = 0; nj < 8; nj++) MMA_F16(acc[mi][nj], af[mi], bf[nj]);
        }

        if ((j & 15) == 15) {
            int tt = bid + (j >> 4) * GPERS;
            int M0 = (tt & 15) * 128;
            int N0 = (tt >> 4) * 256;
#pragma unroll
            for (int mi = 0; mi < 4; mi++) {
#pragma unroll
                for (int nj = 0; nj < 8; nj++) {
                    int c0 = N0 + wn + nj * 8 + (kc << 1);
                    if (c0 < VV) {
                        size_t r0 = (size_t)(M0 + wm + mi * 16 + rr);
                        __stcs((float2*)(C + r0 * VV + c0),
                               make_float2(acc[mi][nj][0] * BSCALE_INV,
                                           acc[mi][nj][1] * BSCALE_INV));
                        __stcs((float2*)(C + (r0 + 8) * VV + c0),
                               make_float2(acc[mi][nj][2] * BSCALE_INV,
                                           acc[mi][nj][3] * BSCALE_INV));
                    }
#pragma unroll
                    for (int k = 0; k < 4; k++) acc[mi][nj][k] = 0.f;
                }
            }
        }
    }
}

// ---------------- launcher ----------------
extern "C" void kernel_launch(void* const* d_in, const int* in_sizes, int n_in,
                              void* d_out, int out_size) {
    const int* idx = (const int*)d_in[0];
    const int* pK = (const int*)d_in[1];
    const float* wte = (const float*)d_in[2];
    const float* wpe = (const float*)d_in[3];
    const float* bseq_w = (const float*)d_in[4];
    const float* logA_seq = (const float*)d_in[5];
    const float* logdt_seq = (const float*)d_in[6];
    const float* bdepth_w = (const float*)d_in[7];
    const float* logA_depth = (const float*)d_in[8];
    const float* logdt_depth = (const float*)d_in[9];
    const float* wpost_w = (const float*)d_in[10];
    const float* wlocal_w = (const float*)d_in[11];
    const float* lowA = (const float*)d_in[12];
    const float* lowB = (const float*)d_in[13];
    const float* lm_head_w = (const float*)d_in[14];
    float* out = (float*)d_out;

    float *x, *h, *ud;
    __half *eh, *hn, *rh, *tmph, *xh, *Bh;
    __half *bseqh, *bdeph, *wposth, *wloch, *lowAh, *lowBh;
    cudaGetSymbolAddress((void**)&x, g_x);
    cudaGetSymbolAddress((void**)&h, g_h);
    cudaGetSymbolAddress((void**)&ud, g_ud);
    cudaGetSymbolAddress((void**)&eh, g_eh);
    cudaGetSymbolAddress((void**)&hn, g_hn);
    cudaGetSymbolAddress((void**)&rh, g_rh);
    cudaGetSymbolAddress((void**)&tmph, g_tmph);
    cudaGetSymbolAddress((void**)&xh, g_xh);
    cudaGetSymbolAddress((void**)&Bh, g_Bh);
    cudaGetSymbolAddress((void**)&bseqh, g_bseqh);
    cudaGetSymbolAddress((void**)&bdeph, g_bdeph);
    cudaGetSymbolAddress((void**)&wposth, g_wposth);
    cudaGetSymbolAddress((void**)&wloch, g_wloch);
    cudaGetSymbolAddress((void**)&lowAh, g_lowAh);
    cudaGetSymbolAddress((void**)&lowBh, g_lowBh);

    cudaFuncSetAttribute(lmhead_gemm, cudaFuncAttributeMaxDynamicSharedMemorySize, LM_SMEM);
    cudaFuncSetAttribute(bd192_f16_kernel, cudaFuncAttributeMaxDynamicSharedMemorySize, BD192_SMEM);

    // weight conversions
    f16_convert_kernel<<<4096, 256>>>(lm_head_w, Bh, VV * DD / 8);
    conv5_f16_kernel<<<dim3(LYR * NBLK * 64 * 64 / 8 / 256, 5), 256>>>(
        bseq_w, bseqh, bdepth_w, bdeph, wlocal_w, wloch, lowA, lowAh, lowB, lowBh);
    conv_f16_kernel<<<LYR * NBLK * 64 * 192 / 8 / 256, 256>>>(wpost_w, wposth);

    embed_kernel<<<TT, 256>>>(idx, wte, wpe, x);

    for (int l = 0; l < LYR; l++) {
        const __half* bseq_l = bseqh + l * NBLK * 64 * 64;
        const __half* bdep_l = bdeph + l * NBLK * 64 * 64;
        const __half* wpost_l = wposth + l * NBLK * 64 * 192;
        const __half* wlocal_l = wloch + l * NBLK * 64 * 64;
        const __half* lowA_l = lowAh + l * DD * RANKK;
        const __half* lowB_l = lowBh + l * RANKK * HH;
        const float* lAs = logA_seq + l * HH;
        const float* lDs = logdt_seq + l * HH;
        const float* lAd = logA_depth + l * (HH - NMEM);
        const float* lDd = logdt_depth + l * (HH - NMEM);

        rmsnorm_f16_kernel<<<TT, 256>>>(x, eh);
        bd64_f16_kernel<<<dim3(TT / 128, NBLK), 256>>>(eh, bseq_l, bdep_l, h, ud);
        scan_fused_kernel<<<DD / 8, dim3(8, NSEG2)>>>(h, lAs, lDs);
        combine_kernel<<<TT, 256>>>(h, ud, lAd, lDd, pK, hn);
        bd192_f16_kernel<<<dim3(TT / 128, NBLK), 256, BD192_SMEM>>>(hn, eh, wpost_l, rh);
        lowrank1_f16_kernel<<<TT / 64, 256>>>(rh, lowB_l, tmph);
        update_f16_kernel<<<dim3(TT / 128, NBLK), 256>>>(x, rh, tmph, wlocal_l, lowA_l);
    }

    rmsnorm_f16_kernel<<<TT, 256>>>(x, xh);
    lmhead_gemm<<<GPERS, 256, LM_SMEM>>>(xh, Bh, out);
}